// round 10
// baseline (speedup 1.0000x reference)
#include <cuda_runtime.h>
#include <math.h>

#define HW 65536
#define BRS (4 * 16 * HW)   // per-branch output stride (4,194,304 floats)

// ---------------- device scratch (no allocation allowed) -------------------
__device__ float g_x   [4 * 16 * HW];   // in_conv output     [b][c][h][w]
__device__ float g_c   [4 * 16 * HW];   // per-branch conv    [b][c][h][w]
__device__ float g_br  [4 * BRS];       // branch outputs     [br][b][c][w][h] (transposed)
__device__ float g_outs[4 * 16 * HW];   // max+mean combined  [b][c][w][h]
__device__ float g_mask[4 * HW];        // sigmoid mask       [b][w][h]
__device__ float g_k3  [256 * 8];       // softmax(scales2)
__device__ float g_k4  [256];           // softmax(scales3)  [g][e]
__device__ float g_s1  [4];             // softmax(scales1)

// ---------------------------------------------------------------------------
__global__ void prep_kernel(const float* __restrict__ s1,
                            const float* __restrict__ s2,
                            const float* __restrict__ s3) {
    int t = threadIdx.x;  // 256 threads
    {
        const float* row = s2 + t * 8;
        float m = row[0];
        #pragma unroll
        for (int j = 1; j < 8; ++j) m = fmaxf(m, row[j]);
        float e[8], sum = 0.f;
        #pragma unroll
        for (int j = 0; j < 8; ++j) { e[j] = expf(row[j] - m); sum += e[j]; }
        float iv = 1.f / sum;
        #pragma unroll
        for (int j = 0; j < 8; ++j) g_k3[t * 8 + j] = e[j] * iv;
    }
    if (t < 16) {
        const float* row = s3 + t * 16;
        float m = row[0];
        #pragma unroll
        for (int j = 1; j < 16; ++j) m = fmaxf(m, row[j]);
        float e[16], sum = 0.f;
        #pragma unroll
        for (int j = 0; j < 16; ++j) { e[j] = expf(row[j] - m); sum += e[j]; }
        float iv = 1.f / sum;
        #pragma unroll
        for (int j = 0; j < 16; ++j) g_k4[t * 16 + j] = e[j] * iv;
    }
    if (t == 0) {
        float m = fmaxf(fmaxf(s1[0], s1[1]), fmaxf(s1[2], s1[3]));
        float e0 = expf(s1[0] - m), e1 = expf(s1[1] - m);
        float e2 = expf(s1[2] - m), e3 = expf(s1[3] - m);
        float iv = 1.f / (e0 + e1 + e2 + e3);
        g_s1[0] = e0 * iv; g_s1[1] = e1 * iv; g_s1[2] = e2 * iv; g_s1[3] = e3 * iv;
    }
}

// ---------------------------------------------------------------------------
// 1x1 conv 64 -> 16 (+bias): one thread per pixel, 16 outputs.
__global__ void in_conv(const float* __restrict__ cen,
                        const float* __restrict__ w,
                        const float* __restrict__ bias) {
    __shared__ float sw[1024];
    __shared__ float sb[16];
    int tid = threadIdx.x;
    for (int i = tid; i < 1024; i += 256) sw[i] = w[i];
    if (tid < 16) sb[tid] = bias[tid];
    __syncthreads();
    int idx = blockIdx.x * 256 + tid;          // 0 .. 262143
    int b = idx >> 16, p = idx & 65535;
    float acc[16];
    #pragma unroll
    for (int c = 0; c < 16; ++c) acc[c] = sb[c];
    const float* cp = cen + (size_t)b * 64 * HW + p;
    #pragma unroll 4
    for (int ci = 0; ci < 64; ++ci) {
        float v = cp[(size_t)ci * HW];
        #pragma unroll
        for (int c = 0; c < 16; ++c) acc[c] = fmaf(sw[c * 64 + ci], v, acc[c]);
    }
    float* xp = g_x + (size_t)b * 16 * HW + p;
    #pragma unroll
    for (int c = 0; c < 16; ++c) xp[(size_t)c * HW] = acc[c];
}

// ---------------------------------------------------------------------------
// KxK conv 16 -> 16 (+bias), SAME padding. Tile 32w x 16h, 256 threads (32,8).
template <int K>
__global__ void mid_conv(const float* __restrict__ w, const float* __restrict__ bias) {
    constexpr int P  = (K - 1) / 2;
    constexpr int TW = 32 + 2 * P;
    constexpr int TH = 16 + 2 * P;
    __shared__ float tile[TH][TW + 1];
    __shared__ float ws[16 * K * K];
    int b  = blockIdx.z;
    int h0 = blockIdx.y * 16, w0 = blockIdx.x * 32;
    int tx = threadIdx.x, ty = threadIdx.y;
    int tid = ty * 32 + tx;
    float acc[16][2];
    #pragma unroll
    for (int co = 0; co < 16; ++co) {
        float bv = __ldg(bias + co);
        acc[co][0] = bv; acc[co][1] = bv;
    }
    for (int ci = 0; ci < 16; ++ci) {
        __syncthreads();
        for (int i = tid; i < 16 * K * K; i += 256) {
            int co = i / (K * K), rc = i % (K * K);
            ws[i] = w[(co * 16 + ci) * K * K + rc];
        }
        const float* xp = g_x + (size_t)(b * 16 + ci) * HW;
        for (int i = tid; i < TH * TW; i += 256) {
            int th = i / TW, tw = i - th * TW;
            int hh = h0 + th - P, wv = w0 + tw - P;
            tile[th][tw] = ((unsigned)hh < 256u && (unsigned)wv < 256u)
                               ? xp[hh * 256 + wv] : 0.f;
        }
        __syncthreads();
        #pragma unroll
        for (int r = 0; r < K; ++r)
            #pragma unroll
            for (int c = 0; c < K; ++c) {
                float v0 = tile[ty + r][tx + c];
                float v1 = tile[ty + 8 + r][tx + c];
                #pragma unroll
                for (int co = 0; co < 16; ++co) {
                    float wv = ws[co * K * K + r * K + c];
                    acc[co][0] = fmaf(wv, v0, acc[co][0]);
                    acc[co][1] = fmaf(wv, v1, acc[co][1]);
                }
            }
    }
    #pragma unroll
    for (int co = 0; co < 16; ++co) {
        float* op = g_c + (size_t)(b * 16 + co) * HW + (h0 + ty) * 256 + w0 + tx;
        op[0]        = acc[co][0];
        op[8 * 256]  = acc[co][1];
    }
}

// ---------------------------------------------------------------------------
// Dual sign-flip bitonic sort: two independent 256-value warp sorts,
// stage-interleaved for ILP. Layout i = lane*8 + r, ascending.
// Opening uses Batcher's 19-comparator sort-8 (exact network).
__device__ __forceinline__ void cmpA(float& a, float& b) {
    float mn = fminf(a, b), mx = fmaxf(a, b); a = mn; b = mx;
}
__device__ __forceinline__ void batcher8x2(float s[8], float t[8]) {
    cmpA(s[0], s[1]); cmpA(t[0], t[1]); cmpA(s[2], s[3]); cmpA(t[2], t[3]);
    cmpA(s[4], s[5]); cmpA(t[4], t[5]); cmpA(s[6], s[7]); cmpA(t[6], t[7]);
    cmpA(s[0], s[2]); cmpA(t[0], t[2]); cmpA(s[1], s[3]); cmpA(t[1], t[3]);
    cmpA(s[4], s[6]); cmpA(t[4], t[6]); cmpA(s[5], s[7]); cmpA(t[5], t[7]);
    cmpA(s[1], s[2]); cmpA(t[1], t[2]); cmpA(s[5], s[6]); cmpA(t[5], t[6]);
    cmpA(s[0], s[4]); cmpA(t[0], t[4]); cmpA(s[2], s[6]); cmpA(t[2], t[6]);
    cmpA(s[1], s[5]); cmpA(t[1], t[5]); cmpA(s[3], s[7]); cmpA(t[3], t[7]);
    cmpA(s[2], s[4]); cmpA(t[2], t[4]); cmpA(s[3], s[5]); cmpA(t[3], t[5]);
    cmpA(s[1], s[2]); cmpA(t[1], t[2]); cmpA(s[3], s[4]); cmpA(t[3], t[4]);
    cmpA(s[5], s[6]); cmpA(t[5], t[6]);
}
__device__ __forceinline__ void inreg3x2(float s[8], float t[8]) {
    cmpA(s[0], s[4]); cmpA(t[0], t[4]); cmpA(s[1], s[5]); cmpA(t[1], t[5]);
    cmpA(s[2], s[6]); cmpA(t[2], t[6]); cmpA(s[3], s[7]); cmpA(t[3], t[7]);
    cmpA(s[0], s[2]); cmpA(t[0], t[2]); cmpA(s[1], s[3]); cmpA(t[1], t[3]);
    cmpA(s[4], s[6]); cmpA(t[4], t[6]); cmpA(s[5], s[7]); cmpA(t[5], t[7]);
    cmpA(s[0], s[1]); cmpA(t[0], t[1]); cmpA(s[2], s[3]); cmpA(t[2], t[3]);
    cmpA(s[4], s[5]); cmpA(t[4], t[5]); cmpA(s[6], s[7]); cmpA(t[6], t[7]);
}
__device__ __forceinline__ void negif2(float s[8], float t[8], int f) {
    float sg = f ? -1.f : 1.f;
    #pragma unroll
    for (int r = 0; r < 8; ++r) { s[r] *= sg; t[r] *= sg; }
}
template <int M>
__device__ __forceinline__ void shufstage2(float s[8], float t[8], bool keepmin) {
    #pragma unroll
    for (int r = 0; r < 8; ++r) {
        float o1 = __shfl_xor_sync(0xffffffffu, s[r], M);
        float o2 = __shfl_xor_sync(0xffffffffu, t[r], M);
        s[r] = keepmin ? fminf(s[r], o1) : fmaxf(s[r], o1);
        t[r] = keepmin ? fminf(t[r], o2) : fmaxf(t[r], o2);
    }
}
__device__ __forceinline__ void sort256x2(float s[8], float t[8], int lane) {
    int b0 = lane & 1, b1 = (lane >> 1) & 1, b2 = (lane >> 2) & 1;
    int b3 = (lane >> 3) & 1, b4 = (lane >> 4) & 1;
    bool k1 = (lane & 1) == 0, k2 = (lane & 2) == 0, k4 = (lane & 4) == 0;
    bool k8 = (lane & 8) == 0, k16 = (lane & 16) == 0;
    // phases 1-3 replaced: flip-domain b0, then exact ascending sort of 8
    negif2(s, t, b0);
    batcher8x2(s, t);
    // phase 4 (flip = b1)
    negif2(s, t, b0 ^ b1);
    shufstage2<1>(s, t, k1);
    inreg3x2(s, t);
    // phase 5 (flip = b2)
    negif2(s, t, b1 ^ b2);
    shufstage2<2>(s, t, k2);
    shufstage2<1>(s, t, k1);
    inreg3x2(s, t);
    // phase 6 (flip = b3)
    negif2(s, t, b2 ^ b3);
    shufstage2<4>(s, t, k4);
    shufstage2<2>(s, t, k2);
    shufstage2<1>(s, t, k1);
    inreg3x2(s, t);
    // phase 7 (flip = b4)
    negif2(s, t, b3 ^ b4);
    shufstage2<8>(s, t, k8);
    shufstage2<4>(s, t, k4);
    shufstage2<2>(s, t, k2);
    shufstage2<1>(s, t, k1);
    inreg3x2(s, t);
    // phase 8 (flip = 0)
    negif2(s, t, b4);
    shufstage2<16>(s, t, k16);
    shufstage2<8>(s, t, k8);
    shufstage2<4>(s, t, k4);
    shufstage2<2>(s, t, k2);
    shufstage2<1>(s, t, k1);
    inreg3x2(s, t);
}

// ---------------------------------------------------------------------------
// Fused: dilated directional diffs -> 16 expansion products -> sort along H
//        -> SiLU -> k4 reduce. Output transposed [b][c][w][h].
// One column per warp; L/C/R columns register-resident in sort layout.
// In-lane taps (S <= r < 8-S region) come from registers; only lane-edge
// rows load their taps directly from shared (clamped, predicated) —
// 6S LDS per ep instead of 64, with NO extra register arrays.
template <int S>
__global__ void __launch_bounds__(256) fused_branch(int br) {
    constexpr int NC = 8 + 2 * S;           // columns in tile
    constexpr int CP = 289;
    __shared__ float cs[NC * CP];
    __shared__ float k3s[128];              // [e][d]
    __shared__ float k4s[16];

    int b = blockIdx.z, g = blockIdx.y, w0 = blockIdx.x * 8;
    int tid  = threadIdx.x;
    int lane = tid & 31, warp = tid >> 5;

    if (tid < 128) k3s[tid] = g_k3[(g * 16 + (tid >> 3)) * 8 + (tid & 7)];
    if (tid < 16) k4s[tid] = g_k4[g * 16 + tid];

    const float* cbase = g_c + (size_t)(b * 16 + g) * HW;
    // w-major fill: consecutive threads hit consecutive gmem addresses
    #pragma unroll 1
    for (int j = tid; j < NC * 256; j += 256) {
        int h   = j / NC;
        int col = j - h * NC;
        int wg  = w0 - S + col;
        float v = 0.f;
        if ((unsigned)wg < 256u) v = cbase[h * 256 + wg];
        cs[col * CP + h + (h >> 3)] = v;
    }
    __syncthreads();

    int colc = warp + S;                    // this warp's output column in tile
    const float* pC = cs + colc * CP;
    const float* pL = cs + (colc - S) * CP;
    const float* pR = cs + (colc + S) * CP;

    // Register-resident columns (sort layout h = lane*8 + r)
    float L[8], C[8], R[8], acc[8];
    #pragma unroll
    for (int r = 0; r < 8; ++r) {
        int h  = lane * 8 + r;
        int ai = h + (h >> 3);
        L[r] = pL[ai]; C[r] = pC[ai]; R[r] = pR[ai];
        acc[r] = 0.f;
    }

    #pragma unroll 1
    for (int ep = 0; ep < 8; ++ep) {
        int e0 = 2 * ep, e1 = 2 * ep + 1;
        float wA[8], wB[8];
        #pragma unroll
        for (int d = 0; d < 8; ++d) { wA[d] = k3s[e0 * 8 + d]; wB[d] = k3s[e1 * 8 + d]; }

        float s[8], t[8];
        #pragma unroll
        for (int r = 0; r < 8; ++r) {
            float lu, cu, ru, ld, cd, rd;
            if (r >= S) {                    // in-lane up taps
                lu = L[r - S]; cu = C[r - S]; ru = R[r - S];
            } else {                         // lane-edge: load from shared
                int hm  = lane * 8 + r - S;
                bool vm = hm >= 0;
                int hmc = vm ? hm : 0;
                int aim = hmc + (hmc >> 3);
                lu = vm ? pL[aim] : 0.f;
                cu = vm ? pC[aim] : 0.f;
                ru = vm ? pR[aim] : 0.f;
            }
            if (r + S < 8) {                 // in-lane down taps
                ld = L[r + S]; cd = C[r + S]; rd = R[r + S];
            } else {
                int hp  = lane * 8 + r + S;
                bool vp = hp < 256;
                int hpc = vp ? hp : 255;
                int aip = hpc + (hpc >> 3);
                ld = vp ? pL[aip] : 0.f;
                cd = vp ? pC[aip] : 0.f;
                rd = vp ? pR[aip] : 0.f;
            }
            float cc = C[r];
            float A0 = lu * wA[0];
            A0 = fmaf(cu, wA[1], A0); A0 = fmaf(ru, wA[2], A0);
            A0 = fmaf(L[r], wA[3], A0); A0 = fmaf(rd, wA[4], A0);
            A0 = fmaf(cd, wA[5], A0); A0 = fmaf(ld, wA[6], A0);
            A0 = fmaf(R[r], wA[7], A0);
            float B0 = rd * wA[0];
            B0 = fmaf(cd, wA[1], B0); B0 = fmaf(ld, wA[2], B0);
            B0 = fmaf(R[r], wA[3], B0); B0 = fmaf(lu, wA[4], B0);
            B0 = fmaf(cu, wA[5], B0); B0 = fmaf(ru, wA[6], B0);
            B0 = fmaf(L[r], wA[7], B0);
            float A1 = lu * wB[0];
            A1 = fmaf(cu, wB[1], A1); A1 = fmaf(ru, wB[2], A1);
            A1 = fmaf(L[r], wB[3], A1); A1 = fmaf(rd, wB[4], A1);
            A1 = fmaf(cd, wB[5], A1); A1 = fmaf(ld, wB[6], A1);
            A1 = fmaf(R[r], wB[7], A1);
            float B1 = rd * wB[0];
            B1 = fmaf(cd, wB[1], B1); B1 = fmaf(ld, wB[2], B1);
            B1 = fmaf(R[r], wB[3], B1); B1 = fmaf(lu, wB[4], B1);
            B1 = fmaf(cu, wB[5], B1); B1 = fmaf(ru, wB[6], B1);
            B1 = fmaf(L[r], wB[7], B1);
            s[r] = (cc - A0) * (cc - B0);
            t[r] = (cc - A1) * (cc - B1);
        }

        sort256x2(s, t, lane);

        float k40 = k4s[e0], k41 = k4s[e1];
        #pragma unroll
        for (int r = 0; r < 8; ++r) {
            float v1 = s[r], v2 = t[r];
            float g1 = 1.f / (1.f + __expf(-v1));
            float g2 = 1.f / (1.f + __expf(-v2));
            acc[r] = fmaf(k40 * v1, g1, acc[r]);
            acc[r] = fmaf(k41 * v2, g2, acc[r]);
        }
    }

    int w = w0 + warp;
    float* op = g_br + (size_t)br * BRS + ((size_t)((b * 16 + g) * 256 + w)) * 256;
    float4 v0 = make_float4(acc[0], acc[1], acc[2], acc[3]);
    float4 v1 = make_float4(acc[4], acc[5], acc[6], acc[7]);
    reinterpret_cast<float4*>(op + lane * 8)[0] = v0;
    reinterpret_cast<float4*>(op + lane * 8)[1] = v1;
}

// ---------------------------------------------------------------------------
__global__ void combine_kernel() {
    int idx = blockIdx.x * 256 + threadIdx.x;   // float4 index
    const float4* p0 = (const float4*)g_br;
    float4 v0 = p0[idx];
    float4 v1 = p0[BRS / 4 + idx];
    float4 v2 = p0[2 * (BRS / 4) + idx];
    float4 v3 = p0[3 * (BRS / 4) + idx];
    float4 o;
    o.x = fmaxf(fmaxf(v0.x, v1.x), fmaxf(v2.x, v3.x)) + 0.25f * (v0.x + v1.x + v2.x + v3.x);
    o.y = fmaxf(fmaxf(v0.y, v1.y), fmaxf(v2.y, v3.y)) + 0.25f * (v0.y + v1.y + v2.y + v3.y);
    o.z = fmaxf(fmaxf(v0.z, v1.z), fmaxf(v2.z, v3.z)) + 0.25f * (v0.z + v1.z + v2.z + v3.z);
    o.w = fmaxf(fmaxf(v0.w, v1.w), fmaxf(v2.w, v3.w)) + 0.25f * (v0.w + v1.w + v2.w + v3.w);
    ((float4*)g_outs)[idx] = o;
}

// ---------------------------------------------------------------------------
// 3x3 conv (no bias) on transposed layout + BN(eval) + SiLU + 1x1 -> sigmoid.
__global__ void post_conv(const float* __restrict__ wb,
                          const float* __restrict__ gamma,
                          const float* __restrict__ beta,
                          const float* __restrict__ mean,
                          const float* __restrict__ var,
                          const float* __restrict__ wout,
                          const float* __restrict__ bout) {
    __shared__ float tile[18][35];
    __shared__ float ws[16 * 9];
    int b  = blockIdx.z;
    int o0 = blockIdx.y * 16, i0 = blockIdx.x * 32;
    int tx = threadIdx.x, ty = threadIdx.y;
    int tid = ty * 32 + tx;
    float acc[16][2];
    #pragma unroll
    for (int co = 0; co < 16; ++co) { acc[co][0] = 0.f; acc[co][1] = 0.f; }
    for (int ci = 0; ci < 16; ++ci) {
        __syncthreads();
        for (int i = tid; i < 144; i += 256) {
            int co = i / 9, rc = i % 9;
            int bi = rc / 3, ao = rc % 3;
            ws[co * 9 + ao * 3 + bi] = wb[(co * 16 + ci) * 9 + bi * 3 + ao];
        }
        const float* xp = g_outs + (size_t)(b * 16 + ci) * HW;
        for (int i = tid; i < 18 * 34; i += 256) {
            int to = i / 34, ti = i - to * 34;
            int oo = o0 + to - 1, ii = i0 + ti - 1;
            tile[to][ti] = ((unsigned)oo < 256u && (unsigned)ii < 256u)
                               ? xp[oo * 256 + ii] : 0.f;
        }
        __syncthreads();
        #pragma unroll
        for (int a = 0; a < 3; ++a)
            #pragma unroll
            for (int bb = 0; bb < 3; ++bb) {
                float v0 = tile[ty + a][tx + bb];
                float v1 = tile[ty + 8 + a][tx + bb];
                #pragma unroll
                for (int co = 0; co < 16; ++co) {
                    float wv = ws[co * 9 + a * 3 + bb];
                    acc[co][0] = fmaf(wv, v0, acc[co][0]);
                    acc[co][1] = fmaf(wv, v1, acc[co][1]);
                }
            }
    }
    float m0 = 0.f, m1 = 0.f;
    #pragma unroll
    for (int co = 0; co < 16; ++co) {
        float sc = __ldg(gamma + co) * rsqrtf(__ldg(var + co) + 1e-5f);
        float sh = __ldg(beta + co) - __ldg(mean + co) * sc;
        float h0 = acc[co][0] * sc + sh;
        float h1 = acc[co][1] * sc + sh;
        h0 = h0 / (1.f + __expf(-h0));
        h1 = h1 / (1.f + __expf(-h1));
        float wv = __ldg(wout + co);
        m0 = fmaf(wv, h0, m0);
        m1 = fmaf(wv, h1, m1);
    }
    float bo = __ldg(bout);
    m0 = 1.f / (1.f + __expf(-(m0 + bo)));
    m1 = 1.f / (1.f + __expf(-(m1 + bo)));
    float* mp = g_mask + (size_t)b * HW + (o0 + ty) * 256 + i0 + tx;
    mp[0]       = m0;
    mp[8 * 256] = m1;
}

// ---------------------------------------------------------------------------
// Final: out = cen * (mask*m*s0 + m*s1 + s2*mask + s3), mask stored [b][w][h].
__global__ void final_kernel(const float* __restrict__ cen,
                             const float* __restrict__ mas,
                             float* __restrict__ out) {
    __shared__ float mt[32][33];
    int b  = blockIdx.z;
    int h0 = blockIdx.x * 32, w0 = blockIdx.y * 32;
    int tx = threadIdx.x, ty = threadIdx.y;
    #pragma unroll
    for (int k = 0; k < 4; ++k) {
        int wi = ty * 4 + k;
        mt[wi][tx] = g_mask[(size_t)b * HW + (w0 + wi) * 256 + h0 + tx];
    }
    __syncthreads();
    float s0 = g_s1[0], s1 = g_s1[1], s2 = g_s1[2], s3 = g_s1[3];
    int w = w0 + tx;
    #pragma unroll
    for (int k = 0; k < 4; ++k) {
        int h = h0 + ty * 4 + k;
        float mv = mt[tx][ty * 4 + k];
        float ms = mas[(size_t)b * HW + h * 256 + w];
        float m  = 1.f / (1.f + __expf(-ms));
        float coef = m * fmaf(mv, s0, s1) + fmaf(s2, mv, s3);
        size_t base = (size_t)b * 64 * HW + (size_t)h * 256 + w;
        #pragma unroll 4
        for (int c = 0; c < 64; ++c) {
            size_t o = base + (size_t)c * HW;
            out[o] = cen[o] * coef;
        }
    }
}

// ---------------------------------------------------------------------------
extern "C" void kernel_launch(void* const* d_in, const int* in_sizes, int n_in,
                              void* d_out, int out_size) {
    const float* cen      = (const float*)d_in[0];
    const float* mas      = (const float*)d_in[1];
    const float* w_in     = (const float*)d_in[2];
    const float* b_in     = (const float*)d_in[3];
    const float* w_c0     = (const float*)d_in[4];
    const float* b_c0     = (const float*)d_in[5];
    const float* w_c1     = (const float*)d_in[6];
    const float* b_c1     = (const float*)d_in[7];
    const float* w_c2     = (const float*)d_in[8];
    const float* b_c2     = (const float*)d_in[9];
    const float* w_c3     = (const float*)d_in[10];
    const float* b_c3     = (const float*)d_in[11];
    const float* scales1  = (const float*)d_in[12];
    const float* scales2  = (const float*)d_in[13];
    const float* scales3  = (const float*)d_in[14];
    const float* w_base   = (const float*)d_in[15];
    const float* bn_gamma = (const float*)d_in[16];
    const float* bn_beta  = (const float*)d_in[17];
    const float* bn_mean  = (const float*)d_in[18];
    const float* bn_var   = (const float*)d_in[19];
    const float* w_out    = (const float*)d_in[20];
    const float* b_out    = (const float*)d_in[21];
    float* out = (float*)d_out;

    prep_kernel<<<1, 256>>>(scales1, scales2, scales3);
    in_conv<<<1024, 256>>>(cen, w_in, b_in);

    dim3 cgrid(8, 16, 4), cblk(32, 8);
    dim3 fgrid(32, 16, 4);

    mid_conv<1><<<cgrid, cblk>>>(w_c0, b_c0);
    fused_branch<1><<<fgrid, 256>>>(0);

    mid_conv<3><<<cgrid, cblk>>>(w_c1, b_c1);
    fused_branch<3><<<fgrid, 256>>>(1);

    mid_conv<5><<<cgrid, cblk>>>(w_c2, b_c2);
    fused_branch<5><<<fgrid, 256>>>(2);

    mid_conv<7><<<cgrid, cblk>>>(w_c3, b_c3);
    fused_branch<7><<<fgrid, 256>>>(3);

    combine_kernel<<<BRS / 1024, 256>>>();

    post_conv<<<cgrid, cblk>>>(w_base, bn_gamma, bn_beta, bn_mean, bn_var,
                               w_out, b_out);

    final_kernel<<<dim3(8, 8, 4), dim3(32, 8)>>>(cen, mas, out);
}

// round 13
// speedup vs baseline: 1.1820x; 1.1820x over previous
#include <cuda_runtime.h>
#include <cuda_fp16.h>
#include <math.h>

#define HW 65536
#define BRS (4 * 16 * HW)   // per-branch output stride (4,194,304 floats)

// ---------------- device scratch (no allocation allowed) -------------------
__device__ float g_x   [4 * 16 * HW];   // in_conv output     [b][c][h][w]
__device__ float g_c   [4 * 16 * HW];   // per-branch conv    [b][c][h][w]
__device__ float g_br  [4 * BRS];       // branch outputs     [br][b][c][w][h] (transposed)
__device__ float g_outs[4 * 16 * HW];   // max+mean combined  [b][c][w][h]
__device__ float g_mask[4 * HW];        // sigmoid mask       [b][w][h]
__device__ float g_k3  [256 * 8];       // softmax(scales2)
__device__ float g_k4  [256];           // softmax(scales3)  [g][e]
__device__ float g_s1  [4];             // softmax(scales1)

// ---------------------------------------------------------------------------
__global__ void prep_kernel(const float* __restrict__ s1,
                            const float* __restrict__ s2,
                            const float* __restrict__ s3) {
    int t = threadIdx.x;  // 256 threads
    {
        const float* row = s2 + t * 8;
        float m = row[0];
        #pragma unroll
        for (int j = 1; j < 8; ++j) m = fmaxf(m, row[j]);
        float e[8], sum = 0.f;
        #pragma unroll
        for (int j = 0; j < 8; ++j) { e[j] = expf(row[j] - m); sum += e[j]; }
        float iv = 1.f / sum;
        #pragma unroll
        for (int j = 0; j < 8; ++j) g_k3[t * 8 + j] = e[j] * iv;
    }
    if (t < 16) {
        const float* row = s3 + t * 16;
        float m = row[0];
        #pragma unroll
        for (int j = 1; j < 16; ++j) m = fmaxf(m, row[j]);
        float e[16], sum = 0.f;
        #pragma unroll
        for (int j = 0; j < 16; ++j) { e[j] = expf(row[j] - m); sum += e[j]; }
        float iv = 1.f / sum;
        #pragma unroll
        for (int j = 0; j < 16; ++j) g_k4[t * 16 + j] = e[j] * iv;
    }
    if (t == 0) {
        float m = fmaxf(fmaxf(s1[0], s1[1]), fmaxf(s1[2], s1[3]));
        float e0 = expf(s1[0] - m), e1 = expf(s1[1] - m);
        float e2 = expf(s1[2] - m), e3 = expf(s1[3] - m);
        float iv = 1.f / (e0 + e1 + e2 + e3);
        g_s1[0] = e0 * iv; g_s1[1] = e1 * iv; g_s1[2] = e2 * iv; g_s1[3] = e3 * iv;
    }
}

// ---------------------------------------------------------------------------
// 1x1 conv 64 -> 16 (+bias): one thread per pixel, 16 outputs.
__global__ void in_conv(const float* __restrict__ cen,
                        const float* __restrict__ w,
                        const float* __restrict__ bias) {
    __shared__ float sw[1024];
    __shared__ float sb[16];
    int tid = threadIdx.x;
    for (int i = tid; i < 1024; i += 256) sw[i] = w[i];
    if (tid < 16) sb[tid] = bias[tid];
    __syncthreads();
    int idx = blockIdx.x * 256 + tid;          // 0 .. 262143
    int b = idx >> 16, p = idx & 65535;
    float acc[16];
    #pragma unroll
    for (int c = 0; c < 16; ++c) acc[c] = sb[c];
    const float* cp = cen + (size_t)b * 64 * HW + p;
    #pragma unroll 4
    for (int ci = 0; ci < 64; ++ci) {
        float v = cp[(size_t)ci * HW];
        #pragma unroll
        for (int c = 0; c < 16; ++c) acc[c] = fmaf(sw[c * 64 + ci], v, acc[c]);
    }
    float* xp = g_x + (size_t)b * 16 * HW + p;
    #pragma unroll
    for (int c = 0; c < 16; ++c) xp[(size_t)c * HW] = acc[c];
}

// ---------------------------------------------------------------------------
// KxK conv 16 -> 16 (+bias), SAME padding. Tile 32w x 16h, 256 threads (32,8).
template <int K>
__global__ void mid_conv(const float* __restrict__ w, const float* __restrict__ bias) {
    constexpr int P  = (K - 1) / 2;
    constexpr int TW = 32 + 2 * P;
    constexpr int TH = 16 + 2 * P;
    __shared__ float tile[TH][TW + 1];
    __shared__ float ws[16 * K * K];
    int b  = blockIdx.z;
    int h0 = blockIdx.y * 16, w0 = blockIdx.x * 32;
    int tx = threadIdx.x, ty = threadIdx.y;
    int tid = ty * 32 + tx;
    float acc[16][2];
    #pragma unroll
    for (int co = 0; co < 16; ++co) {
        float bv = __ldg(bias + co);
        acc[co][0] = bv; acc[co][1] = bv;
    }
    for (int ci = 0; ci < 16; ++ci) {
        __syncthreads();
        for (int i = tid; i < 16 * K * K; i += 256) {
            int co = i / (K * K), rc = i % (K * K);
            ws[i] = w[(co * 16 + ci) * K * K + rc];
        }
        const float* xp = g_x + (size_t)(b * 16 + ci) * HW;
        for (int i = tid; i < TH * TW; i += 256) {
            int th = i / TW, tw = i - th * TW;
            int hh = h0 + th - P, wv = w0 + tw - P;
            tile[th][tw] = ((unsigned)hh < 256u && (unsigned)wv < 256u)
                               ? xp[hh * 256 + wv] : 0.f;
        }
        __syncthreads();
        #pragma unroll
        for (int r = 0; r < K; ++r)
            #pragma unroll
            for (int c = 0; c < K; ++c) {
                float v0 = tile[ty + r][tx + c];
                float v1 = tile[ty + 8 + r][tx + c];
                #pragma unroll
                for (int co = 0; co < 16; ++co) {
                    float wv = ws[co * K * K + r * K + c];
                    acc[co][0] = fmaf(wv, v0, acc[co][0]);
                    acc[co][1] = fmaf(wv, v1, acc[co][1]);
                }
            }
    }
    #pragma unroll
    for (int co = 0; co < 16; ++co) {
        float* op = g_c + (size_t)(b * 16 + co) * HW + (h0 + ty) * 256 + w0 + tx;
        op[0]        = acc[co][0];
        op[8 * 256]  = acc[co][1];
    }
}

// ---------------------------------------------------------------------------
// bit-cast helpers for shfl on __half2 (pure register reinterpretation)
__device__ __forceinline__ unsigned h2_as_u32(__half2 h) {
    return *reinterpret_cast<unsigned*>(&h);
}
__device__ __forceinline__ __half2 u32_as_h2(unsigned u) {
    return *reinterpret_cast<__half2*>(&u);
}

// ---------------------------------------------------------------------------
// Packed fp16x2 dual sign-flip bitonic sort: each __half2 register carries two
// independent channels; two packed arrays (s, t) interleave for ILP, so one
// call sorts FOUR channels. Layout i = lane*8 + r, ascending per half.
__device__ __forceinline__ void cmpA2(__half2& a, __half2& b) {
    __half2 mn = __hmin2(a, b), mx = __hmax2(a, b); a = mn; b = mx;
}
__device__ __forceinline__ void batcher8x2h(__half2 s[8], __half2 t[8]) {
    cmpA2(s[0], s[1]); cmpA2(t[0], t[1]); cmpA2(s[2], s[3]); cmpA2(t[2], t[3]);
    cmpA2(s[4], s[5]); cmpA2(t[4], t[5]); cmpA2(s[6], s[7]); cmpA2(t[6], t[7]);
    cmpA2(s[0], s[2]); cmpA2(t[0], t[2]); cmpA2(s[1], s[3]); cmpA2(t[1], t[3]);
    cmpA2(s[4], s[6]); cmpA2(t[4], t[6]); cmpA2(s[5], s[7]); cmpA2(t[5], t[7]);
    cmpA2(s[1], s[2]); cmpA2(t[1], t[2]); cmpA2(s[5], s[6]); cmpA2(t[5], t[6]);
    cmpA2(s[0], s[4]); cmpA2(t[0], t[4]); cmpA2(s[2], s[6]); cmpA2(t[2], t[6]);
    cmpA2(s[1], s[5]); cmpA2(t[1], t[5]); cmpA2(s[3], s[7]); cmpA2(t[3], t[7]);
    cmpA2(s[2], s[4]); cmpA2(t[2], t[4]); cmpA2(s[3], s[5]); cmpA2(t[3], t[5]);
    cmpA2(s[1], s[2]); cmpA2(t[1], t[2]); cmpA2(s[3], s[4]); cmpA2(t[3], t[4]);
    cmpA2(s[5], s[6]); cmpA2(t[5], t[6]);
}
__device__ __forceinline__ void inreg3x2h(__half2 s[8], __half2 t[8]) {
    cmpA2(s[0], s[4]); cmpA2(t[0], t[4]); cmpA2(s[1], s[5]); cmpA2(t[1], t[5]);
    cmpA2(s[2], s[6]); cmpA2(t[2], t[6]); cmpA2(s[3], s[7]); cmpA2(t[3], t[7]);
    cmpA2(s[0], s[2]); cmpA2(t[0], t[2]); cmpA2(s[1], s[3]); cmpA2(t[1], t[3]);
    cmpA2(s[4], s[6]); cmpA2(t[4], t[6]); cmpA2(s[5], s[7]); cmpA2(t[5], t[7]);
    cmpA2(s[0], s[1]); cmpA2(t[0], t[1]); cmpA2(s[2], s[3]); cmpA2(t[2], t[3]);
    cmpA2(s[4], s[5]); cmpA2(t[4], t[5]); cmpA2(s[6], s[7]); cmpA2(t[6], t[7]);
}
__device__ __forceinline__ void negif2h(__half2 s[8], __half2 t[8], int f) {
    __half2 sg = f ? __float2half2_rn(-1.f) : __float2half2_rn(1.f);
    #pragma unroll
    for (int r = 0; r < 8; ++r) { s[r] = __hmul2(s[r], sg); t[r] = __hmul2(t[r], sg); }
}
template <int M>
__device__ __forceinline__ void shufstage2h(__half2 s[8], __half2 t[8], bool keepmin) {
    #pragma unroll
    for (int r = 0; r < 8; ++r) {
        unsigned o1 = __shfl_xor_sync(0xffffffffu, h2_as_u32(s[r]), M);
        unsigned o2 = __shfl_xor_sync(0xffffffffu, h2_as_u32(t[r]), M);
        __half2 v1 = u32_as_h2(o1);
        __half2 v2 = u32_as_h2(o2);
        s[r] = keepmin ? __hmin2(s[r], v1) : __hmax2(s[r], v1);
        t[r] = keepmin ? __hmin2(t[r], v2) : __hmax2(t[r], v2);
    }
}
__device__ __forceinline__ void sort256x2h(__half2 s[8], __half2 t[8], int lane) {
    int b0 = lane & 1, b1 = (lane >> 1) & 1, b2 = (lane >> 2) & 1;
    int b3 = (lane >> 3) & 1, b4 = (lane >> 4) & 1;
    bool k1 = (lane & 1) == 0, k2 = (lane & 2) == 0, k4 = (lane & 4) == 0;
    bool k8 = (lane & 8) == 0, k16 = (lane & 16) == 0;
    negif2h(s, t, b0);
    batcher8x2h(s, t);
    negif2h(s, t, b0 ^ b1);
    shufstage2h<1>(s, t, k1);
    inreg3x2h(s, t);
    negif2h(s, t, b1 ^ b2);
    shufstage2h<2>(s, t, k2);
    shufstage2h<1>(s, t, k1);
    inreg3x2h(s, t);
    negif2h(s, t, b2 ^ b3);
    shufstage2h<4>(s, t, k4);
    shufstage2h<2>(s, t, k2);
    shufstage2h<1>(s, t, k1);
    inreg3x2h(s, t);
    negif2h(s, t, b3 ^ b4);
    shufstage2h<8>(s, t, k8);
    shufstage2h<4>(s, t, k4);
    shufstage2h<2>(s, t, k2);
    shufstage2h<1>(s, t, k1);
    inreg3x2h(s, t);
    negif2h(s, t, b4);
    shufstage2h<16>(s, t, k16);
    shufstage2h<8>(s, t, k8);
    shufstage2h<4>(s, t, k4);
    shufstage2h<2>(s, t, k2);
    shufstage2h<1>(s, t, k1);
    inreg3x2h(s, t);
}

// ---------------------------------------------------------------------------
// Fused: dilated directional diffs -> 16 expansion products -> sort along H
//        -> SiLU -> k4 reduce. Output transposed [b][c][w][h].
// One column per warp; L/C/R columns register-resident in sort layout; lane-
// edge taps from shared. Four e-channels per iteration sorted as two packed
// fp16x2 arrays. Products fp32 -> fp16 for sorting (rel-err budget 1e-3);
// silu in fp32 via __expf.
template <int S>
__global__ void __launch_bounds__(256) fused_branch(int br) {
    constexpr int NC = 8 + 2 * S;           // columns in tile
    constexpr int CP = 289;
    __shared__ float cs[NC * CP];
    __shared__ float k3s[128];              // [e][d]
    __shared__ float k4s[16];

    int b = blockIdx.z, g = blockIdx.y, w0 = blockIdx.x * 8;
    int tid  = threadIdx.x;
    int lane = tid & 31, warp = tid >> 5;

    if (tid < 128) k3s[tid] = g_k3[(g * 16 + (tid >> 3)) * 8 + (tid & 7)];
    if (tid < 16) k4s[tid] = g_k4[g * 16 + tid];

    const float* cbase = g_c + (size_t)(b * 16 + g) * HW;
    #pragma unroll 1
    for (int j = tid; j < NC * 256; j += 256) {
        int h   = j / NC;
        int col = j - h * NC;
        int wg  = w0 - S + col;
        float v = 0.f;
        if ((unsigned)wg < 256u) v = cbase[h * 256 + wg];
        cs[col * CP + h + (h >> 3)] = v;
    }
    __syncthreads();

    int colc = warp + S;
    const float* pC = cs + colc * CP;
    const float* pL = cs + (colc - S) * CP;
    const float* pR = cs + (colc + S) * CP;

    float L[8], C[8], R[8], acc[8];
    #pragma unroll
    for (int r = 0; r < 8; ++r) {
        int h  = lane * 8 + r;
        int ai = h + (h >> 3);
        L[r] = pL[ai]; C[r] = pC[ai]; R[r] = pR[ai];
        acc[r] = 0.f;
    }

    #pragma unroll 1
    for (int ep = 0; ep < 4; ++ep) {
        int e0 = 4 * ep;
        float wA[8], wB[8], wC2[8], wD[8];
        #pragma unroll
        for (int d = 0; d < 8; ++d) {
            wA[d]  = k3s[(e0 + 0) * 8 + d];
            wB[d]  = k3s[(e0 + 1) * 8 + d];
            wC2[d] = k3s[(e0 + 2) * 8 + d];
            wD[d]  = k3s[(e0 + 3) * 8 + d];
        }

        __half2 s[8], t[8];
        #pragma unroll
        for (int r = 0; r < 8; ++r) {
            float lu, cu, ru, ld, cd, rd;
            if (r >= S) {
                lu = L[r - S]; cu = C[r - S]; ru = R[r - S];
            } else {
                int hm  = lane * 8 + r - S;
                bool vm = hm >= 0;
                int hmc = vm ? hm : 0;
                int aim = hmc + (hmc >> 3);
                lu = vm ? pL[aim] : 0.f;
                cu = vm ? pC[aim] : 0.f;
                ru = vm ? pR[aim] : 0.f;
            }
            if (r + S < 8) {
                ld = L[r + S]; cd = C[r + S]; rd = R[r + S];
            } else {
                int hp  = lane * 8 + r + S;
                bool vp = hp < 256;
                int hpc = vp ? hp : 255;
                int aip = hpc + (hpc >> 3);
                ld = vp ? pL[aip] : 0.f;
                cd = vp ? pC[aip] : 0.f;
                rd = vp ? pR[aip] : 0.f;
            }
            float cc = C[r];
            float pr[4];
            #pragma unroll
            for (int q = 0; q < 4; ++q) {
                const float* wq = (q == 0) ? wA : (q == 1) ? wB : (q == 2) ? wC2 : wD;
                float A = lu * wq[0];
                A = fmaf(cu, wq[1], A); A = fmaf(ru, wq[2], A);
                A = fmaf(L[r], wq[3], A); A = fmaf(rd, wq[4], A);
                A = fmaf(cd, wq[5], A); A = fmaf(ld, wq[6], A);
                A = fmaf(R[r], wq[7], A);
                float Bv = rd * wq[0];
                Bv = fmaf(cd, wq[1], Bv); Bv = fmaf(ld, wq[2], Bv);
                Bv = fmaf(R[r], wq[3], Bv); Bv = fmaf(lu, wq[4], Bv);
                Bv = fmaf(cu, wq[5], Bv); Bv = fmaf(ru, wq[6], Bv);
                Bv = fmaf(L[r], wq[7], Bv);
                pr[q] = (cc - A) * (cc - Bv);
            }
            s[r] = __floats2half2_rn(pr[0], pr[1]);
            t[r] = __floats2half2_rn(pr[2], pr[3]);
        }

        sort256x2h(s, t, lane);

        float k40 = k4s[e0 + 0], k41 = k4s[e0 + 1];
        float k42 = k4s[e0 + 2], k43 = k4s[e0 + 3];
        #pragma unroll
        for (int r = 0; r < 8; ++r) {
            float v0 = __low2float(s[r]),  v1 = __high2float(s[r]);
            float v2 = __low2float(t[r]),  v3 = __high2float(t[r]);
            float g0 = 1.f / (1.f + __expf(-v0));
            float g1 = 1.f / (1.f + __expf(-v1));
            float g2 = 1.f / (1.f + __expf(-v2));
            float g3 = 1.f / (1.f + __expf(-v3));
            float a = acc[r];
            a = fmaf(k40 * v0, g0, a);
            a = fmaf(k41 * v1, g1, a);
            a = fmaf(k42 * v2, g2, a);
            a = fmaf(k43 * v3, g3, a);
            acc[r] = a;
        }
    }

    int w = w0 + warp;
    float* op = g_br + (size_t)br * BRS + ((size_t)((b * 16 + g) * 256 + w)) * 256;
    float4 v0 = make_float4(acc[0], acc[1], acc[2], acc[3]);
    float4 v1 = make_float4(acc[4], acc[5], acc[6], acc[7]);
    reinterpret_cast<float4*>(op + lane * 8)[0] = v0;
    reinterpret_cast<float4*>(op + lane * 8)[1] = v1;
}

// ---------------------------------------------------------------------------
__global__ void combine_kernel() {
    int idx = blockIdx.x * 256 + threadIdx.x;   // float4 index
    const float4* p0 = (const float4*)g_br;
    float4 v0 = p0[idx];
    float4 v1 = p0[BRS / 4 + idx];
    float4 v2 = p0[2 * (BRS / 4) + idx];
    float4 v3 = p0[3 * (BRS / 4) + idx];
    float4 o;
    o.x = fmaxf(fmaxf(v0.x, v1.x), fmaxf(v2.x, v3.x)) + 0.25f * (v0.x + v1.x + v2.x + v3.x);
    o.y = fmaxf(fmaxf(v0.y, v1.y), fmaxf(v2.y, v3.y)) + 0.25f * (v0.y + v1.y + v2.y + v3.y);
    o.z = fmaxf(fmaxf(v0.z, v1.z), fmaxf(v2.z, v3.z)) + 0.25f * (v0.z + v1.z + v2.z + v3.z);
    o.w = fmaxf(fmaxf(v0.w, v1.w), fmaxf(v2.w, v3.w)) + 0.25f * (v0.w + v1.w + v2.w + v3.w);
    ((float4*)g_outs)[idx] = o;
}

// ---------------------------------------------------------------------------
// 3x3 conv (no bias) on transposed layout + BN(eval) + SiLU + 1x1 -> sigmoid.
__global__ void post_conv(const float* __restrict__ wb,
                          const float* __restrict__ gamma,
                          const float* __restrict__ beta,
                          const float* __restrict__ mean,
                          const float* __restrict__ var,
                          const float* __restrict__ wout,
                          const float* __restrict__ bout) {
    __shared__ float tile[18][35];
    __shared__ float ws[16 * 9];
    int b  = blockIdx.z;
    int o0 = blockIdx.y * 16, i0 = blockIdx.x * 32;
    int tx = threadIdx.x, ty = threadIdx.y;
    int tid = ty * 32 + tx;
    float acc[16][2];
    #pragma unroll
    for (int co = 0; co < 16; ++co) { acc[co][0] = 0.f; acc[co][1] = 0.f; }
    for (int ci = 0; ci < 16; ++ci) {
        __syncthreads();
        for (int i = tid; i < 144; i += 256) {
            int co = i / 9, rc = i % 9;
            int bi = rc / 3, ao = rc % 3;
            ws[co * 9 + ao * 3 + bi] = wb[(co * 16 + ci) * 9 + bi * 3 + ao];
        }
        const float* xp = g_outs + (size_t)(b * 16 + ci) * HW;
        for (int i = tid; i < 18 * 34; i += 256) {
            int to = i / 34, ti = i - to * 34;
            int oo = o0 + to - 1, ii = i0 + ti - 1;
            tile[to][ti] = ((unsigned)oo < 256u && (unsigned)ii < 256u)
                               ? xp[oo * 256 + ii] : 0.f;
        }
        __syncthreads();
        #pragma unroll
        for (int a = 0; a < 3; ++a)
            #pragma unroll
            for (int bb = 0; bb < 3; ++bb) {
                float v0 = tile[ty + a][tx + bb];
                float v1 = tile[ty + 8 + a][tx + bb];
                #pragma unroll
                for (int co = 0; co < 16; ++co) {
                    float wv = ws[co * 9 + a * 3 + bb];
                    acc[co][0] = fmaf(wv, v0, acc[co][0]);
                    acc[co][1] = fmaf(wv, v1, acc[co][1]);
                }
            }
    }
    float m0 = 0.f, m1 = 0.f;
    #pragma unroll
    for (int co = 0; co < 16; ++co) {
        float sc = __ldg(gamma + co) * rsqrtf(__ldg(var + co) + 1e-5f);
        float sh = __ldg(beta + co) - __ldg(mean + co) * sc;
        float h0 = acc[co][0] * sc + sh;
        float h1 = acc[co][1] * sc + sh;
        h0 = h0 / (1.f + __expf(-h0));
        h1 = h1 / (1.f + __expf(-h1));
        float wv = __ldg(wout + co);
        m0 = fmaf(wv, h0, m0);
        m1 = fmaf(wv, h1, m1);
    }
    float bo = __ldg(bout);
    m0 = 1.f / (1.f + __expf(-(m0 + bo)));
    m1 = 1.f / (1.f + __expf(-(m1 + bo)));
    float* mp = g_mask + (size_t)b * HW + (o0 + ty) * 256 + i0 + tx;
    mp[0]       = m0;
    mp[8 * 256] = m1;
}

// ---------------------------------------------------------------------------
// Final: out = cen * (mask*m*s0 + m*s1 + s2*mask + s3), mask stored [b][w][h].
__global__ void final_kernel(const float* __restrict__ cen,
                             const float* __restrict__ mas,
                             float* __restrict__ out) {
    __shared__ float mt[32][33];
    int b  = blockIdx.z;
    int h0 = blockIdx.x * 32, w0 = blockIdx.y * 32;
    int tx = threadIdx.x, ty = threadIdx.y;
    #pragma unroll
    for (int k = 0; k < 4; ++k) {
        int wi = ty * 4 + k;
        mt[wi][tx] = g_mask[(size_t)b * HW + (w0 + wi) * 256 + h0 + tx];
    }
    __syncthreads();
    float s0 = g_s1[0], s1 = g_s1[1], s2 = g_s1[2], s3 = g_s1[3];
    int w = w0 + tx;
    #pragma unroll
    for (int k = 0; k < 4; ++k) {
        int h = h0 + ty * 4 + k;
        float mv = mt[tx][ty * 4 + k];
        float ms = mas[(size_t)b * HW + h * 256 + w];
        float m  = 1.f / (1.f + __expf(-ms));
        float coef = m * fmaf(mv, s0, s1) + fmaf(s2, mv, s3);
        size_t base = (size_t)b * 64 * HW + (size_t)h * 256 + w;
        #pragma unroll 4
        for (int c = 0; c < 64; ++c) {
            size_t o = base + (size_t)c * HW;
            out[o] = cen[o] * coef;
        }
    }
}

// ---------------------------------------------------------------------------
extern "C" void kernel_launch(void* const* d_in, const int* in_sizes, int n_in,
                              void* d_out, int out_size) {
    const float* cen      = (const float*)d_in[0];
    const float* mas      = (const float*)d_in[1];
    const float* w_in     = (const float*)d_in[2];
    const float* b_in     = (const float*)d_in[3];
    const float* w_c0     = (const float*)d_in[4];
    const float* b_c0     = (const float*)d_in[5];
    const float* w_c1     = (const float*)d_in[6];
    const float* b_c1     = (const float*)d_in[7];
    const float* w_c2     = (const float*)d_in[8];
    const float* b_c2     = (const float*)d_in[9];
    const float* w_c3     = (const float*)d_in[10];
    const float* b_c3     = (const float*)d_in[11];
    const float* scales1  = (const float*)d_in[12];
    const float* scales2  = (const float*)d_in[13];
    const float* scales3  = (const float*)d_in[14];
    const float* w_base   = (const float*)d_in[15];
    const float* bn_gamma = (const float*)d_in[16];
    const float* bn_beta  = (const float*)d_in[17];
    const float* bn_mean  = (const float*)d_in[18];
    const float* bn_var   = (const float*)d_in[19];
    const float* w_out    = (const float*)d_in[20];
    const float* b_out    = (const float*)d_in[21];
    float* out = (float*)d_out;

    prep_kernel<<<1, 256>>>(scales1, scales2, scales3);
    in_conv<<<1024, 256>>>(cen, w_in, b_in);

    dim3 cgrid(8, 16, 4), cblk(32, 8);
    dim3 fgrid(32, 16, 4);

    mid_conv<1><<<cgrid, cblk>>>(w_c0, b_c0);
    fused_branch<1><<<fgrid, 256>>>(0);

    mid_conv<3><<<cgrid, cblk>>>(w_c1, b_c1);
    fused_branch<3><<<fgrid, 256>>>(1);

    mid_conv<5><<<cgrid, cblk>>>(w_c2, b_c2);
    fused_branch<5><<<fgrid, 256>>>(2);

    mid_conv<7><<<cgrid, cblk>>>(w_c3, b_c3);
    fused_branch<7><<<fgrid, 256>>>(3);

    combine_kernel<<<BRS / 1024, 256>>>();

    post_conv<<<cgrid, cblk>>>(w_base, bn_gamma, bn_beta, bn_mean, bn_var,
                               w_out, b_out);

    final_kernel<<<dim3(8, 8, 4), dim3(32, 8)>>>(cen, mas, out);
}

// round 14
// speedup vs baseline: 1.3495x; 1.1417x over previous
#include <cuda_runtime.h>
#include <cuda_fp16.h>
#include <math.h>

#define HW 65536
#define BRS (4 * 16 * HW)   // per-branch output stride (4,194,304 floats)

// ---------------- device scratch (no allocation allowed) -------------------
__device__ float g_x   [4 * 16 * HW];   // in_conv output     [b][c][h][w]
__device__ float g_c   [4 * 16 * HW];   // per-branch conv    [b][c][h][w]
__device__ float g_br  [4 * BRS];       // branch outputs     [br][b][c][w][h] (transposed)
__device__ float g_outs[4 * 16 * HW];   // max+mean combined  [b][c][w][h]
__device__ float g_mask[4 * HW];        // sigmoid mask       [b][w][h]
__device__ float g_k3  [256 * 8];       // softmax(scales2)
__device__ float g_k4  [256];           // softmax(scales3)  [g][e]
__device__ float g_s1  [4];             // softmax(scales1)

// ---------------------------------------------------------------------------
__global__ void prep_kernel(const float* __restrict__ s1,
                            const float* __restrict__ s2,
                            const float* __restrict__ s3) {
    int t = threadIdx.x;  // 256 threads
    {
        const float* row = s2 + t * 8;
        float m = row[0];
        #pragma unroll
        for (int j = 1; j < 8; ++j) m = fmaxf(m, row[j]);
        float e[8], sum = 0.f;
        #pragma unroll
        for (int j = 0; j < 8; ++j) { e[j] = expf(row[j] - m); sum += e[j]; }
        float iv = 1.f / sum;
        #pragma unroll
        for (int j = 0; j < 8; ++j) g_k3[t * 8 + j] = e[j] * iv;
    }
    if (t < 16) {
        const float* row = s3 + t * 16;
        float m = row[0];
        #pragma unroll
        for (int j = 1; j < 16; ++j) m = fmaxf(m, row[j]);
        float e[16], sum = 0.f;
        #pragma unroll
        for (int j = 0; j < 16; ++j) { e[j] = expf(row[j] - m); sum += e[j]; }
        float iv = 1.f / sum;
        #pragma unroll
        for (int j = 0; j < 16; ++j) g_k4[t * 16 + j] = e[j] * iv;
    }
    if (t == 0) {
        float m = fmaxf(fmaxf(s1[0], s1[1]), fmaxf(s1[2], s1[3]));
        float e0 = expf(s1[0] - m), e1 = expf(s1[1] - m);
        float e2 = expf(s1[2] - m), e3 = expf(s1[3] - m);
        float iv = 1.f / (e0 + e1 + e2 + e3);
        g_s1[0] = e0 * iv; g_s1[1] = e1 * iv; g_s1[2] = e2 * iv; g_s1[3] = e3 * iv;
    }
}

// ---------------------------------------------------------------------------
// 1x1 conv 64 -> 16 (+bias): one thread per pixel, 16 outputs.
__global__ void in_conv(const float* __restrict__ cen,
                        const float* __restrict__ w,
                        const float* __restrict__ bias) {
    __shared__ float sw[1024];
    __shared__ float sb[16];
    int tid = threadIdx.x;
    for (int i = tid; i < 1024; i += 256) sw[i] = w[i];
    if (tid < 16) sb[tid] = bias[tid];
    __syncthreads();
    int idx = blockIdx.x * 256 + tid;          // 0 .. 262143
    int b = idx >> 16, p = idx & 65535;
    float acc[16];
    #pragma unroll
    for (int c = 0; c < 16; ++c) acc[c] = sb[c];
    const float* cp = cen + (size_t)b * 64 * HW + p;
    #pragma unroll 4
    for (int ci = 0; ci < 64; ++ci) {
        float v = cp[(size_t)ci * HW];
        #pragma unroll
        for (int c = 0; c < 16; ++c) acc[c] = fmaf(sw[c * 64 + ci], v, acc[c]);
    }
    float* xp = g_x + (size_t)b * 16 * HW + p;
    #pragma unroll
    for (int c = 0; c < 16; ++c) xp[(size_t)c * HW] = acc[c];
}

// ---------------------------------------------------------------------------
// KxK conv 16 -> 16 (+bias), SAME padding. Tile 32w x 16h, 256 threads (32,8).
template <int K>
__global__ void mid_conv(const float* __restrict__ w, const float* __restrict__ bias) {
    constexpr int P  = (K - 1) / 2;
    constexpr int TW = 32 + 2 * P;
    constexpr int TH = 16 + 2 * P;
    __shared__ float tile[TH][TW + 1];
    __shared__ float ws[16 * K * K];
    int b  = blockIdx.z;
    int h0 = blockIdx.y * 16, w0 = blockIdx.x * 32;
    int tx = threadIdx.x, ty = threadIdx.y;
    int tid = ty * 32 + tx;
    float acc[16][2];
    #pragma unroll
    for (int co = 0; co < 16; ++co) {
        float bv = __ldg(bias + co);
        acc[co][0] = bv; acc[co][1] = bv;
    }
    for (int ci = 0; ci < 16; ++ci) {
        __syncthreads();
        for (int i = tid; i < 16 * K * K; i += 256) {
            int co = i / (K * K), rc = i % (K * K);
            ws[i] = w[(co * 16 + ci) * K * K + rc];
        }
        const float* xp = g_x + (size_t)(b * 16 + ci) * HW;
        for (int i = tid; i < TH * TW; i += 256) {
            int th = i / TW, tw = i - th * TW;
            int hh = h0 + th - P, wv = w0 + tw - P;
            tile[th][tw] = ((unsigned)hh < 256u && (unsigned)wv < 256u)
                               ? xp[hh * 256 + wv] : 0.f;
        }
        __syncthreads();
        #pragma unroll
        for (int r = 0; r < K; ++r)
            #pragma unroll
            for (int c = 0; c < K; ++c) {
                float v0 = tile[ty + r][tx + c];
                float v1 = tile[ty + 8 + r][tx + c];
                #pragma unroll
                for (int co = 0; co < 16; ++co) {
                    float wv = ws[co * K * K + r * K + c];
                    acc[co][0] = fmaf(wv, v0, acc[co][0]);
                    acc[co][1] = fmaf(wv, v1, acc[co][1]);
                }
            }
    }
    #pragma unroll
    for (int co = 0; co < 16; ++co) {
        float* op = g_c + (size_t)(b * 16 + co) * HW + (h0 + ty) * 256 + w0 + tx;
        op[0]        = acc[co][0];
        op[8 * 256]  = acc[co][1];
    }
}

// ---------------------------------------------------------------------------
// bit-cast helpers for shfl on __half2 (pure register reinterpretation)
__device__ __forceinline__ unsigned h2_as_u32(__half2 h) {
    return *reinterpret_cast<unsigned*>(&h);
}
__device__ __forceinline__ __half2 u32_as_h2(unsigned u) {
    return *reinterpret_cast<__half2*>(&u);
}

// ---------------------------------------------------------------------------
// Packed fp16x2 dual sign-flip bitonic sort: each __half2 register carries two
// independent channels; two packed arrays (s, t) interleave for ILP, so one
// call sorts FOUR channels. Layout i = lane*8 + r, ascending per half.
__device__ __forceinline__ void cmpA2(__half2& a, __half2& b) {
    __half2 mn = __hmin2(a, b), mx = __hmax2(a, b); a = mn; b = mx;
}
__device__ __forceinline__ void batcher8x2h(__half2 s[8], __half2 t[8]) {
    cmpA2(s[0], s[1]); cmpA2(t[0], t[1]); cmpA2(s[2], s[3]); cmpA2(t[2], t[3]);
    cmpA2(s[4], s[5]); cmpA2(t[4], t[5]); cmpA2(s[6], s[7]); cmpA2(t[6], t[7]);
    cmpA2(s[0], s[2]); cmpA2(t[0], t[2]); cmpA2(s[1], s[3]); cmpA2(t[1], t[3]);
    cmpA2(s[4], s[6]); cmpA2(t[4], t[6]); cmpA2(s[5], s[7]); cmpA2(t[5], t[7]);
    cmpA2(s[1], s[2]); cmpA2(t[1], t[2]); cmpA2(s[5], s[6]); cmpA2(t[5], t[6]);
    cmpA2(s[0], s[4]); cmpA2(t[0], t[4]); cmpA2(s[2], s[6]); cmpA2(t[2], t[6]);
    cmpA2(s[1], s[5]); cmpA2(t[1], t[5]); cmpA2(s[3], s[7]); cmpA2(t[3], t[7]);
    cmpA2(s[2], s[4]); cmpA2(t[2], t[4]); cmpA2(s[3], s[5]); cmpA2(t[3], t[5]);
    cmpA2(s[1], s[2]); cmpA2(t[1], t[2]); cmpA2(s[3], s[4]); cmpA2(t[3], t[4]);
    cmpA2(s[5], s[6]); cmpA2(t[5], t[6]);
}
__device__ __forceinline__ void inreg3x2h(__half2 s[8], __half2 t[8]) {
    cmpA2(s[0], s[4]); cmpA2(t[0], t[4]); cmpA2(s[1], s[5]); cmpA2(t[1], t[5]);
    cmpA2(s[2], s[6]); cmpA2(t[2], t[6]); cmpA2(s[3], s[7]); cmpA2(t[3], t[7]);
    cmpA2(s[0], s[2]); cmpA2(t[0], t[2]); cmpA2(s[1], s[3]); cmpA2(t[1], t[3]);
    cmpA2(s[4], s[6]); cmpA2(t[4], t[6]); cmpA2(s[5], s[7]); cmpA2(t[5], t[7]);
    cmpA2(s[0], s[1]); cmpA2(t[0], t[1]); cmpA2(s[2], s[3]); cmpA2(t[2], t[3]);
    cmpA2(s[4], s[5]); cmpA2(t[4], t[5]); cmpA2(s[6], s[7]); cmpA2(t[6], t[7]);
}
__device__ __forceinline__ void negif2h(__half2 s[8], __half2 t[8], int f) {
    __half2 sg = f ? __float2half2_rn(-1.f) : __float2half2_rn(1.f);
    #pragma unroll
    for (int r = 0; r < 8; ++r) { s[r] = __hmul2(s[r], sg); t[r] = __hmul2(t[r], sg); }
}
template <int M>
__device__ __forceinline__ void shufstage2h(__half2 s[8], __half2 t[8], bool keepmin) {
    #pragma unroll
    for (int r = 0; r < 8; ++r) {
        unsigned o1 = __shfl_xor_sync(0xffffffffu, h2_as_u32(s[r]), M);
        unsigned o2 = __shfl_xor_sync(0xffffffffu, h2_as_u32(t[r]), M);
        __half2 v1 = u32_as_h2(o1);
        __half2 v2 = u32_as_h2(o2);
        s[r] = keepmin ? __hmin2(s[r], v1) : __hmax2(s[r], v1);
        t[r] = keepmin ? __hmin2(t[r], v2) : __hmax2(t[r], v2);
    }
}
__device__ __forceinline__ void sort256x2h(__half2 s[8], __half2 t[8], int lane) {
    int b0 = lane & 1, b1 = (lane >> 1) & 1, b2 = (lane >> 2) & 1;
    int b3 = (lane >> 3) & 1, b4 = (lane >> 4) & 1;
    bool k1 = (lane & 1) == 0, k2 = (lane & 2) == 0, k4 = (lane & 4) == 0;
    bool k8 = (lane & 8) == 0, k16 = (lane & 16) == 0;
    negif2h(s, t, b0);
    batcher8x2h(s, t);
    negif2h(s, t, b0 ^ b1);
    shufstage2h<1>(s, t, k1);
    inreg3x2h(s, t);
    negif2h(s, t, b1 ^ b2);
    shufstage2h<2>(s, t, k2);
    shufstage2h<1>(s, t, k1);
    inreg3x2h(s, t);
    negif2h(s, t, b2 ^ b3);
    shufstage2h<4>(s, t, k4);
    shufstage2h<2>(s, t, k2);
    shufstage2h<1>(s, t, k1);
    inreg3x2h(s, t);
    negif2h(s, t, b3 ^ b4);
    shufstage2h<8>(s, t, k8);
    shufstage2h<4>(s, t, k4);
    shufstage2h<2>(s, t, k2);
    shufstage2h<1>(s, t, k1);
    inreg3x2h(s, t);
    negif2h(s, t, b4);
    shufstage2h<16>(s, t, k16);
    shufstage2h<8>(s, t, k8);
    shufstage2h<4>(s, t, k4);
    shufstage2h<2>(s, t, k2);
    shufstage2h<1>(s, t, k1);
    inreg3x2h(s, t);
}

// ---------------------------------------------------------------------------
// Fused: dilated directional diffs -> 16 expansion products -> sort along H
//        -> SiLU -> k4 reduce. Output transposed [b][c][w][h].
// One column per warp. Taps held as BROADCAST half2 registers; weights packed
// per channel-pair as half2 in shared. Products computed fully in fp16x2
// (hfma2 chains), landing directly in sort format. Four channels/iteration
// via two interleaved packed sorts. Epilogue fp32.
template <int S>
__global__ void __launch_bounds__(256, 3) fused_branch(int br) {
    constexpr int NC = 8 + 2 * S;           // columns in tile
    constexpr int CP = 289;
    __shared__ float cs[NC * CP];
    __shared__ __half2 k3h[64];             // [pair p][d] = {k3[2p][d], k3[2p+1][d]}
    __shared__ float k4s[16];

    int b = blockIdx.z, g = blockIdx.y, w0 = blockIdx.x * 8;
    int tid  = threadIdx.x;
    int lane = tid & 31, warp = tid >> 5;

    if (tid < 64) {
        int p = tid >> 3, d = tid & 7;
        int row = g * 16 + 2 * p;
        k3h[tid] = __floats2half2_rn(g_k3[row * 8 + d], g_k3[(row + 1) * 8 + d]);
    }
    if (tid < 16) k4s[tid] = g_k4[g * 16 + tid];

    const float* cbase = g_c + (size_t)(b * 16 + g) * HW;
    #pragma unroll 1
    for (int j = tid; j < NC * 256; j += 256) {
        int h   = j / NC;
        int col = j - h * NC;
        int wg  = w0 - S + col;
        float v = 0.f;
        if ((unsigned)wg < 256u) v = cbase[h * 256 + wg];
        cs[col * CP + h + (h >> 3)] = v;
    }
    __syncthreads();

    int colc = warp + S;
    const float* pC = cs + colc * CP;
    const float* pL = cs + (colc - S) * CP;
    const float* pR = cs + (colc + S) * CP;

    // Broadcast-half2 register-resident columns (sort layout h = lane*8 + r)
    __half2 Lh[8], Ch[8], Rh[8];
    float acc[8];
    #pragma unroll
    for (int r = 0; r < 8; ++r) {
        int h  = lane * 8 + r;
        int ai = h + (h >> 3);
        Lh[r] = __float2half2_rn(pL[ai]);
        Ch[r] = __float2half2_rn(pC[ai]);
        Rh[r] = __float2half2_rn(pR[ai]);
        acc[r] = 0.f;
    }

    #pragma unroll 1
    for (int ep = 0; ep < 4; ++ep) {
        // pair A = channels (4ep, 4ep+1); pair B = channels (4ep+2, 4ep+3)
        __half2 whA[8], whB[8];
        #pragma unroll
        for (int d = 0; d < 8; ++d) {
            whA[d] = k3h[(2 * ep)     * 8 + d];
            whB[d] = k3h[(2 * ep + 1) * 8 + d];
        }

        __half2 s[8], t[8];
        #pragma unroll
        for (int r = 0; r < 8; ++r) {
            __half2 luh, cuh, ruh, ldh, cdh, rdh;
            if (r >= S) {
                luh = Lh[r - S]; cuh = Ch[r - S]; ruh = Rh[r - S];
            } else {
                int hm  = lane * 8 + r - S;
                bool vm = hm >= 0;
                int hmc = vm ? hm : 0;
                int aim = hmc + (hmc >> 3);
                luh = __float2half2_rn(vm ? pL[aim] : 0.f);
                cuh = __float2half2_rn(vm ? pC[aim] : 0.f);
                ruh = __float2half2_rn(vm ? pR[aim] : 0.f);
            }
            if (r + S < 8) {
                ldh = Lh[r + S]; cdh = Ch[r + S]; rdh = Rh[r + S];
            } else {
                int hp  = lane * 8 + r + S;
                bool vp = hp < 256;
                int hpc = vp ? hp : 255;
                int aip = hpc + (hpc >> 3);
                ldh = __float2half2_rn(vp ? pL[aip] : 0.f);
                cdh = __float2half2_rn(vp ? pC[aip] : 0.f);
                rdh = __float2half2_rn(vp ? pR[aip] : 0.f);
            }
            __half2 cch = Ch[r], Lrh = Lh[r], Rrh = Rh[r];

            // pair A: forward taps (lu,cu,ru,L,rd,cd,ld,R), rotated (d^4)
            __half2 A0 = __hmul2(luh, whA[0]);
            A0 = __hfma2(cuh, whA[1], A0); A0 = __hfma2(ruh, whA[2], A0);
            A0 = __hfma2(Lrh, whA[3], A0); A0 = __hfma2(rdh, whA[4], A0);
            A0 = __hfma2(cdh, whA[5], A0); A0 = __hfma2(ldh, whA[6], A0);
            A0 = __hfma2(Rrh, whA[7], A0);
            __half2 B0 = __hmul2(rdh, whA[0]);
            B0 = __hfma2(cdh, whA[1], B0); B0 = __hfma2(ldh, whA[2], B0);
            B0 = __hfma2(Rrh, whA[3], B0); B0 = __hfma2(luh, whA[4], B0);
            B0 = __hfma2(cuh, whA[5], B0); B0 = __hfma2(ruh, whA[6], B0);
            B0 = __hfma2(Lrh, whA[7], B0);
            s[r] = __hmul2(__hsub2(cch, A0), __hsub2(cch, B0));

            __half2 A1 = __hmul2(luh, whB[0]);
            A1 = __hfma2(cuh, whB[1], A1); A1 = __hfma2(ruh, whB[2], A1);
            A1 = __hfma2(Lrh, whB[3], A1); A1 = __hfma2(rdh, whB[4], A1);
            A1 = __hfma2(cdh, whB[5], A1); A1 = __hfma2(ldh, whB[6], A1);
            A1 = __hfma2(Rrh, whB[7], A1);
            __half2 B1 = __hmul2(rdh, whB[0]);
            B1 = __hfma2(cdh, whB[1], B1); B1 = __hfma2(ldh, whB[2], B1);
            B1 = __hfma2(Rrh, whB[3], B1); B1 = __hfma2(luh, whB[4], B1);
            B1 = __hfma2(cuh, whB[5], B1); B1 = __hfma2(ruh, whB[6], B1);
            B1 = __hfma2(Lrh, whB[7], B1);
            t[r] = __hmul2(__hsub2(cch, A1), __hsub2(cch, B1));
        }

        sort256x2h(s, t, lane);

        int e0 = 4 * ep;
        float k40 = k4s[e0 + 0], k41 = k4s[e0 + 1];
        float k42 = k4s[e0 + 2], k43 = k4s[e0 + 3];
        #pragma unroll
        for (int r = 0; r < 8; ++r) {
            float v0 = __low2float(s[r]),  v1 = __high2float(s[r]);
            float v2 = __low2float(t[r]),  v3 = __high2float(t[r]);
            float g0 = 1.f / (1.f + __expf(-v0));
            float g1 = 1.f / (1.f + __expf(-v1));
            float g2 = 1.f / (1.f + __expf(-v2));
            float g3 = 1.f / (1.f + __expf(-v3));
            float a = acc[r];
            a = fmaf(k40 * v0, g0, a);
            a = fmaf(k41 * v1, g1, a);
            a = fmaf(k42 * v2, g2, a);
            a = fmaf(k43 * v3, g3, a);
            acc[r] = a;
        }
    }

    int w = w0 + warp;
    float* op = g_br + (size_t)br * BRS + ((size_t)((b * 16 + g) * 256 + w)) * 256;
    float4 v0 = make_float4(acc[0], acc[1], acc[2], acc[3]);
    float4 v1 = make_float4(acc[4], acc[5], acc[6], acc[7]);
    reinterpret_cast<float4*>(op + lane * 8)[0] = v0;
    reinterpret_cast<float4*>(op + lane * 8)[1] = v1;
}

// ---------------------------------------------------------------------------
__global__ void combine_kernel() {
    int idx = blockIdx.x * 256 + threadIdx.x;   // float4 index
    const float4* p0 = (const float4*)g_br;
    float4 v0 = p0[idx];
    float4 v1 = p0[BRS / 4 + idx];
    float4 v2 = p0[2 * (BRS / 4) + idx];
    float4 v3 = p0[3 * (BRS / 4) + idx];
    float4 o;
    o.x = fmaxf(fmaxf(v0.x, v1.x), fmaxf(v2.x, v3.x)) + 0.25f * (v0.x + v1.x + v2.x + v3.x);
    o.y = fmaxf(fmaxf(v0.y, v1.y), fmaxf(v2.y, v3.y)) + 0.25f * (v0.y + v1.y + v2.y + v3.y);
    o.z = fmaxf(fmaxf(v0.z, v1.z), fmaxf(v2.z, v3.z)) + 0.25f * (v0.z + v1.z + v2.z + v3.z);
    o.w = fmaxf(fmaxf(v0.w, v1.w), fmaxf(v2.w, v3.w)) + 0.25f * (v0.w + v1.w + v2.w + v3.w);
    ((float4*)g_outs)[idx] = o;
}

// ---------------------------------------------------------------------------
// 3x3 conv (no bias) on transposed layout + BN(eval) + SiLU + 1x1 -> sigmoid.
__global__ void post_conv(const float* __restrict__ wb,
                          const float* __restrict__ gamma,
                          const float* __restrict__ beta,
                          const float* __restrict__ mean,
                          const float* __restrict__ var,
                          const float* __restrict__ wout,
                          const float* __restrict__ bout) {
    __shared__ float tile[18][35];
    __shared__ float ws[16 * 9];
    int b  = blockIdx.z;
    int o0 = blockIdx.y * 16, i0 = blockIdx.x * 32;
    int tx = threadIdx.x, ty = threadIdx.y;
    int tid = ty * 32 + tx;
    float acc[16][2];
    #pragma unroll
    for (int co = 0; co < 16; ++co) { acc[co][0] = 0.f; acc[co][1] = 0.f; }
    for (int ci = 0; ci < 16; ++ci) {
        __syncthreads();
        for (int i = tid; i < 144; i += 256) {
            int co = i / 9, rc = i % 9;
            int bi = rc / 3, ao = rc % 3;
            ws[co * 9 + ao * 3 + bi] = wb[(co * 16 + ci) * 9 + bi * 3 + ao];
        }
        const float* xp = g_outs + (size_t)(b * 16 + ci) * HW;
        for (int i = tid; i < 18 * 34; i += 256) {
            int to = i / 34, ti = i - to * 34;
            int oo = o0 + to - 1, ii = i0 + ti - 1;
            tile[to][ti] = ((unsigned)oo < 256u && (unsigned)ii < 256u)
                               ? xp[oo * 256 + ii] : 0.f;
        }
        __syncthreads();
        #pragma unroll
        for (int a = 0; a < 3; ++a)
            #pragma unroll
            for (int bb = 0; bb < 3; ++bb) {
                float v0 = tile[ty + a][tx + bb];
                float v1 = tile[ty + 8 + a][tx + bb];
                #pragma unroll
                for (int co = 0; co < 16; ++co) {
                    float wv = ws[co * 9 + a * 3 + bb];
                    acc[co][0] = fmaf(wv, v0, acc[co][0]);
                    acc[co][1] = fmaf(wv, v1, acc[co][1]);
                }
            }
    }
    float m0 = 0.f, m1 = 0.f;
    #pragma unroll
    for (int co = 0; co < 16; ++co) {
        float sc = __ldg(gamma + co) * rsqrtf(__ldg(var + co) + 1e-5f);
        float sh = __ldg(beta + co) - __ldg(mean + co) * sc;
        float h0 = acc[co][0] * sc + sh;
        float h1 = acc[co][1] * sc + sh;
        h0 = h0 / (1.f + __expf(-h0));
        h1 = h1 / (1.f + __expf(-h1));
        float wv = __ldg(wout + co);
        m0 = fmaf(wv, h0, m0);
        m1 = fmaf(wv, h1, m1);
    }
    float bo = __ldg(bout);
    m0 = 1.f / (1.f + __expf(-(m0 + bo)));
    m1 = 1.f / (1.f + __expf(-(m1 + bo)));
    float* mp = g_mask + (size_t)b * HW + (o0 + ty) * 256 + i0 + tx;
    mp[0]       = m0;
    mp[8 * 256] = m1;
}

// ---------------------------------------------------------------------------
// Final: out = cen * (mask*m*s0 + m*s1 + s2*mask + s3), mask stored [b][w][h].
__global__ void final_kernel(const float* __restrict__ cen,
                             const float* __restrict__ mas,
                             float* __restrict__ out) {
    __shared__ float mt[32][33];
    int b  = blockIdx.z;
    int h0 = blockIdx.x * 32, w0 = blockIdx.y * 32;
    int tx = threadIdx.x, ty = threadIdx.y;
    #pragma unroll
    for (int k = 0; k < 4; ++k) {
        int wi = ty * 4 + k;
        mt[wi][tx] = g_mask[(size_t)b * HW + (w0 + wi) * 256 + h0 + tx];
    }
    __syncthreads();
    float s0 = g_s1[0], s1 = g_s1[1], s2 = g_s1[2], s3 = g_s1[3];
    int w = w0 + tx;
    #pragma unroll
    for (int k = 0; k < 4; ++k) {
        int h = h0 + ty * 4 + k;
        float mv = mt[tx][ty * 4 + k];
        float ms = mas[(size_t)b * HW + h * 256 + w];
        float m  = 1.f / (1.f + __expf(-ms));
        float coef = m * fmaf(mv, s0, s1) + fmaf(s2, mv, s3);
        size_t base = (size_t)b * 64 * HW + (size_t)h * 256 + w;
        #pragma unroll 4
        for (int c = 0; c < 64; ++c) {
            size_t o = base + (size_t)c * HW;
            out[o] = cen[o] * coef;
        }
    }
}

// ---------------------------------------------------------------------------
extern "C" void kernel_launch(void* const* d_in, const int* in_sizes, int n_in,
                              void* d_out, int out_size) {
    const float* cen      = (const float*)d_in[0];
    const float* mas      = (const float*)d_in[1];
    const float* w_in     = (const float*)d_in[2];
    const float* b_in     = (const float*)d_in[3];
    const float* w_c0     = (const float*)d_in[4];
    const float* b_c0     = (const float*)d_in[5];
    const float* w_c1     = (const float*)d_in[6];
    const float* b_c1     = (const float*)d_in[7];
    const float* w_c2     = (const float*)d_in[8];
    const float* b_c2     = (const float*)d_in[9];
    const float* w_c3     = (const float*)d_in[10];
    const float* b_c3     = (const float*)d_in[11];
    const float* scales1  = (const float*)d_in[12];
    const float* scales2  = (const float*)d_in[13];
    const float* scales3  = (const float*)d_in[14];
    const float* w_base   = (const float*)d_in[15];
    const float* bn_gamma = (const float*)d_in[16];
    const float* bn_beta  = (const float*)d_in[17];
    const float* bn_mean  = (const float*)d_in[18];
    const float* bn_var   = (const float*)d_in[19];
    const float* w_out    = (const float*)d_in[20];
    const float* b_out    = (const float*)d_in[21];
    float* out = (float*)d_out;

    prep_kernel<<<1, 256>>>(scales1, scales2, scales3);
    in_conv<<<1024, 256>>>(cen, w_in, b_in);

    dim3 cgrid(8, 16, 4), cblk(32, 8);
    dim3 fgrid(32, 16, 4);

    mid_conv<1><<<cgrid, cblk>>>(w_c0, b_c0);
    fused_branch<1><<<fgrid, 256>>>(0);

    mid_conv<3><<<cgrid, cblk>>>(w_c1, b_c1);
    fused_branch<3><<<fgrid, 256>>>(1);

    mid_conv<5><<<cgrid, cblk>>>(w_c2, b_c2);
    fused_branch<5><<<fgrid, 256>>>(2);

    mid_conv<7><<<cgrid, cblk>>>(w_c3, b_c3);
    fused_branch<7><<<fgrid, 256>>>(3);

    combine_kernel<<<BRS / 1024, 256>>>();

    post_conv<<<cgrid, cblk>>>(w_base, bn_gamma, bn_beta, bn_mean, bn_var,
                               w_out, b_out);

    final_kernel<<<dim3(8, 8, 4), dim3(32, 8)>>>(cen, mas, out);
}

// round 15
// speedup vs baseline: 1.3871x; 1.0278x over previous
#include <cuda_runtime.h>
#include <cuda_fp16.h>
#include <math.h>

#define HW 65536
#define BRS (4 * 16 * HW)   // per-branch output stride (4,194,304 elements)

// ---------------- device scratch (no allocation allowed) -------------------
__device__ float  g_x   [4 * 16 * HW];  // in_conv output     [b][c][h][w]
__device__ float  g_c   [4 * 16 * HW];  // per-branch conv    [b][c][h][w]
__device__ __half g_brh [4 * BRS];      // branch outputs     [br][b][c][w][h] (half)
__device__ float  g_mask[4 * HW];       // sigmoid mask       [b][w][h]
__device__ float  g_k3  [256 * 8];      // softmax(scales2)
__device__ float  g_k4  [256];          // softmax(scales3)  [g][e]
__device__ float  g_s1  [4];            // softmax(scales1)

// ---------------------------------------------------------------------------
__global__ void prep_kernel(const float* __restrict__ s1,
                            const float* __restrict__ s2,
                            const float* __restrict__ s3) {
    int t = threadIdx.x;  // 256 threads
    {
        const float* row = s2 + t * 8;
        float m = row[0];
        #pragma unroll
        for (int j = 1; j < 8; ++j) m = fmaxf(m, row[j]);
        float e[8], sum = 0.f;
        #pragma unroll
        for (int j = 0; j < 8; ++j) { e[j] = expf(row[j] - m); sum += e[j]; }
        float iv = 1.f / sum;
        #pragma unroll
        for (int j = 0; j < 8; ++j) g_k3[t * 8 + j] = e[j] * iv;
    }
    if (t < 16) {
        const float* row = s3 + t * 16;
        float m = row[0];
        #pragma unroll
        for (int j = 1; j < 16; ++j) m = fmaxf(m, row[j]);
        float e[16], sum = 0.f;
        #pragma unroll
        for (int j = 0; j < 16; ++j) { e[j] = expf(row[j] - m); sum += e[j]; }
        float iv = 1.f / sum;
        #pragma unroll
        for (int j = 0; j < 16; ++j) g_k4[t * 16 + j] = e[j] * iv;
    }
    if (t == 0) {
        float m = fmaxf(fmaxf(s1[0], s1[1]), fmaxf(s1[2], s1[3]));
        float e0 = expf(s1[0] - m), e1 = expf(s1[1] - m);
        float e2 = expf(s1[2] - m), e3 = expf(s1[3] - m);
        float iv = 1.f / (e0 + e1 + e2 + e3);
        g_s1[0] = e0 * iv; g_s1[1] = e1 * iv; g_s1[2] = e2 * iv; g_s1[3] = e3 * iv;
    }
}

// ---------------------------------------------------------------------------
// 1x1 conv 64 -> 16 (+bias): one thread per pixel, 16 outputs.
__global__ void in_conv(const float* __restrict__ cen,
                        const float* __restrict__ w,
                        const float* __restrict__ bias) {
    __shared__ float sw[1024];
    __shared__ float sb[16];
    int tid = threadIdx.x;
    for (int i = tid; i < 1024; i += 256) sw[i] = w[i];
    if (tid < 16) sb[tid] = bias[tid];
    __syncthreads();
    int idx = blockIdx.x * 256 + tid;          // 0 .. 262143
    int b = idx >> 16, p = idx & 65535;
    float acc[16];
    #pragma unroll
    for (int c = 0; c < 16; ++c) acc[c] = sb[c];
    const float* cp = cen + (size_t)b * 64 * HW + p;
    #pragma unroll 4
    for (int ci = 0; ci < 64; ++ci) {
        float v = cp[(size_t)ci * HW];
        #pragma unroll
        for (int c = 0; c < 16; ++c) acc[c] = fmaf(sw[c * 64 + ci], v, acc[c]);
    }
    float* xp = g_x + (size_t)b * 16 * HW + p;
    #pragma unroll
    for (int c = 0; c < 16; ++c) xp[(size_t)c * HW] = acc[c];
}

// ---------------------------------------------------------------------------
// KxK conv 16 -> 16 (+bias), SAME padding. Tile 32w x 16h, 256 threads (32,8).
template <int K>
__global__ void mid_conv(const float* __restrict__ w, const float* __restrict__ bias) {
    constexpr int P  = (K - 1) / 2;
    constexpr int TW = 32 + 2 * P;
    constexpr int TH = 16 + 2 * P;
    __shared__ float tile[TH][TW + 1];
    __shared__ float ws[16 * K * K];
    int b  = blockIdx.z;
    int h0 = blockIdx.y * 16, w0 = blockIdx.x * 32;
    int tx = threadIdx.x, ty = threadIdx.y;
    int tid = ty * 32 + tx;
    float acc[16][2];
    #pragma unroll
    for (int co = 0; co < 16; ++co) {
        float bv = __ldg(bias + co);
        acc[co][0] = bv; acc[co][1] = bv;
    }
    for (int ci = 0; ci < 16; ++ci) {
        __syncthreads();
        for (int i = tid; i < 16 * K * K; i += 256) {
            int co = i / (K * K), rc = i % (K * K);
            ws[i] = w[(co * 16 + ci) * K * K + rc];
        }
        const float* xp = g_x + (size_t)(b * 16 + ci) * HW;
        for (int i = tid; i < TH * TW; i += 256) {
            int th = i / TW, tw = i - th * TW;
            int hh = h0 + th - P, wv = w0 + tw - P;
            tile[th][tw] = ((unsigned)hh < 256u && (unsigned)wv < 256u)
                               ? xp[hh * 256 + wv] : 0.f;
        }
        __syncthreads();
        #pragma unroll
        for (int r = 0; r < K; ++r)
            #pragma unroll
            for (int c = 0; c < K; ++c) {
                float v0 = tile[ty + r][tx + c];
                float v1 = tile[ty + 8 + r][tx + c];
                #pragma unroll
                for (int co = 0; co < 16; ++co) {
                    float wv = ws[co * K * K + r * K + c];
                    acc[co][0] = fmaf(wv, v0, acc[co][0]);
                    acc[co][1] = fmaf(wv, v1, acc[co][1]);
                }
            }
    }
    #pragma unroll
    for (int co = 0; co < 16; ++co) {
        float* op = g_c + (size_t)(b * 16 + co) * HW + (h0 + ty) * 256 + w0 + tx;
        op[0]        = acc[co][0];
        op[8 * 256]  = acc[co][1];
    }
}

// ---------------------------------------------------------------------------
// bit-cast helpers for shfl on __half2 (pure register reinterpretation)
__device__ __forceinline__ unsigned h2_as_u32(__half2 h) {
    return *reinterpret_cast<unsigned*>(&h);
}
__device__ __forceinline__ __half2 u32_as_h2(unsigned u) {
    return *reinterpret_cast<__half2*>(&u);
}

// ---------------------------------------------------------------------------
// Packed fp16x2 dual sign-flip bitonic sort (two interleaved packed arrays =
// four channels per call). Layout i = lane*8 + r, ascending per half.
__device__ __forceinline__ void cmpA2(__half2& a, __half2& b) {
    __half2 mn = __hmin2(a, b), mx = __hmax2(a, b); a = mn; b = mx;
}
__device__ __forceinline__ void batcher8x2h(__half2 s[8], __half2 t[8]) {
    cmpA2(s[0], s[1]); cmpA2(t[0], t[1]); cmpA2(s[2], s[3]); cmpA2(t[2], t[3]);
    cmpA2(s[4], s[5]); cmpA2(t[4], t[5]); cmpA2(s[6], s[7]); cmpA2(t[6], t[7]);
    cmpA2(s[0], s[2]); cmpA2(t[0], t[2]); cmpA2(s[1], s[3]); cmpA2(t[1], t[3]);
    cmpA2(s[4], s[6]); cmpA2(t[4], t[6]); cmpA2(s[5], s[7]); cmpA2(t[5], t[7]);
    cmpA2(s[1], s[2]); cmpA2(t[1], t[2]); cmpA2(s[5], s[6]); cmpA2(t[5], t[6]);
    cmpA2(s[0], s[4]); cmpA2(t[0], t[4]); cmpA2(s[2], s[6]); cmpA2(t[2], t[6]);
    cmpA2(s[1], s[5]); cmpA2(t[1], t[5]); cmpA2(s[3], s[7]); cmpA2(t[3], t[7]);
    cmpA2(s[2], s[4]); cmpA2(t[2], t[4]); cmpA2(s[3], s[5]); cmpA2(t[3], t[5]);
    cmpA2(s[1], s[2]); cmpA2(t[1], t[2]); cmpA2(s[3], s[4]); cmpA2(t[3], t[4]);
    cmpA2(s[5], s[6]); cmpA2(t[5], t[6]);
}
__device__ __forceinline__ void inreg3x2h(__half2 s[8], __half2 t[8]) {
    cmpA2(s[0], s[4]); cmpA2(t[0], t[4]); cmpA2(s[1], s[5]); cmpA2(t[1], t[5]);
    cmpA2(s[2], s[6]); cmpA2(t[2], t[6]); cmpA2(s[3], s[7]); cmpA2(t[3], t[7]);
    cmpA2(s[0], s[2]); cmpA2(t[0], t[2]); cmpA2(s[1], s[3]); cmpA2(t[1], t[3]);
    cmpA2(s[4], s[6]); cmpA2(t[4], t[6]); cmpA2(s[5], s[7]); cmpA2(t[5], t[7]);
    cmpA2(s[0], s[1]); cmpA2(t[0], t[1]); cmpA2(s[2], s[3]); cmpA2(t[2], t[3]);
    cmpA2(s[4], s[5]); cmpA2(t[4], t[5]); cmpA2(s[6], s[7]); cmpA2(t[6], t[7]);
}
__device__ __forceinline__ void negif2h(__half2 s[8], __half2 t[8], int f) {
    __half2 sg = f ? __float2half2_rn(-1.f) : __float2half2_rn(1.f);
    #pragma unroll
    for (int r = 0; r < 8; ++r) { s[r] = __hmul2(s[r], sg); t[r] = __hmul2(t[r], sg); }
}
template <int M>
__device__ __forceinline__ void shufstage2h(__half2 s[8], __half2 t[8], bool keepmin) {
    #pragma unroll
    for (int r = 0; r < 8; ++r) {
        unsigned o1 = __shfl_xor_sync(0xffffffffu, h2_as_u32(s[r]), M);
        unsigned o2 = __shfl_xor_sync(0xffffffffu, h2_as_u32(t[r]), M);
        __half2 v1 = u32_as_h2(o1);
        __half2 v2 = u32_as_h2(o2);
        s[r] = keepmin ? __hmin2(s[r], v1) : __hmax2(s[r], v1);
        t[r] = keepmin ? __hmin2(t[r], v2) : __hmax2(t[r], v2);
    }
}
__device__ __forceinline__ void sort256x2h(__half2 s[8], __half2 t[8], int lane) {
    int b0 = lane & 1, b1 = (lane >> 1) & 1, b2 = (lane >> 2) & 1;
    int b3 = (lane >> 3) & 1, b4 = (lane >> 4) & 1;
    bool k1 = (lane & 1) == 0, k2 = (lane & 2) == 0, k4 = (lane & 4) == 0;
    bool k8 = (lane & 8) == 0, k16 = (lane & 16) == 0;
    negif2h(s, t, b0);
    batcher8x2h(s, t);
    negif2h(s, t, b0 ^ b1);
    shufstage2h<1>(s, t, k1);
    inreg3x2h(s, t);
    negif2h(s, t, b1 ^ b2);
    shufstage2h<2>(s, t, k2);
    shufstage2h<1>(s, t, k1);
    inreg3x2h(s, t);
    negif2h(s, t, b2 ^ b3);
    shufstage2h<4>(s, t, k4);
    shufstage2h<2>(s, t, k2);
    shufstage2h<1>(s, t, k1);
    inreg3x2h(s, t);
    negif2h(s, t, b3 ^ b4);
    shufstage2h<8>(s, t, k8);
    shufstage2h<4>(s, t, k4);
    shufstage2h<2>(s, t, k2);
    shufstage2h<1>(s, t, k1);
    inreg3x2h(s, t);
    negif2h(s, t, b4);
    shufstage2h<16>(s, t, k16);
    shufstage2h<8>(s, t, k8);
    shufstage2h<4>(s, t, k4);
    shufstage2h<2>(s, t, k2);
    shufstage2h<1>(s, t, k1);
    inreg3x2h(s, t);
}

// ---------------------------------------------------------------------------
// Fused branch: taps broadcast-half2, products in hfma2, packed sort, fp32
// epilogue; output packed half (one 16B store per lane).
template <int S>
__global__ void __launch_bounds__(256, 3) fused_branch(int br) {
    constexpr int NC = 8 + 2 * S;           // columns in tile
    constexpr int CP = 289;
    __shared__ float cs[NC * CP];
    __shared__ __half2 k3h[64];             // [pair p][d] = {k3[2p][d], k3[2p+1][d]}
    __shared__ float k4s[16];

    int b = blockIdx.z, g = blockIdx.y, w0 = blockIdx.x * 8;
    int tid  = threadIdx.x;
    int lane = tid & 31, warp = tid >> 5;

    if (tid < 64) {
        int p = tid >> 3, d = tid & 7;
        int row = g * 16 + 2 * p;
        k3h[tid] = __floats2half2_rn(g_k3[row * 8 + d], g_k3[(row + 1) * 8 + d]);
    }
    if (tid < 16) k4s[tid] = g_k4[g * 16 + tid];

    const float* cbase = g_c + (size_t)(b * 16 + g) * HW;
    #pragma unroll 1
    for (int j = tid; j < NC * 256; j += 256) {
        int h   = j / NC;
        int col = j - h * NC;
        int wg  = w0 - S + col;
        float v = 0.f;
        if ((unsigned)wg < 256u) v = cbase[h * 256 + wg];
        cs[col * CP + h + (h >> 3)] = v;
    }
    __syncthreads();

    int colc = warp + S;
    const float* pC = cs + colc * CP;
    const float* pL = cs + (colc - S) * CP;
    const float* pR = cs + (colc + S) * CP;

    __half2 Lh[8], Ch[8], Rh[8];
    float acc[8];
    #pragma unroll
    for (int r = 0; r < 8; ++r) {
        int h  = lane * 8 + r;
        int ai = h + (h >> 3);
        Lh[r] = __float2half2_rn(pL[ai]);
        Ch[r] = __float2half2_rn(pC[ai]);
        Rh[r] = __float2half2_rn(pR[ai]);
        acc[r] = 0.f;
    }

    #pragma unroll 1
    for (int ep = 0; ep < 4; ++ep) {
        __half2 whA[8], whB[8];
        #pragma unroll
        for (int d = 0; d < 8; ++d) {
            whA[d] = k3h[(2 * ep)     * 8 + d];
            whB[d] = k3h[(2 * ep + 1) * 8 + d];
        }

        __half2 s[8], t[8];
        #pragma unroll
        for (int r = 0; r < 8; ++r) {
            __half2 luh, cuh, ruh, ldh, cdh, rdh;
            if (r >= S) {
                luh = Lh[r - S]; cuh = Ch[r - S]; ruh = Rh[r - S];
            } else {
                int hm  = lane * 8 + r - S;
                bool vm = hm >= 0;
                int hmc = vm ? hm : 0;
                int aim = hmc + (hmc >> 3);
                luh = __float2half2_rn(vm ? pL[aim] : 0.f);
                cuh = __float2half2_rn(vm ? pC[aim] : 0.f);
                ruh = __float2half2_rn(vm ? pR[aim] : 0.f);
            }
            if (r + S < 8) {
                ldh = Lh[r + S]; cdh = Ch[r + S]; rdh = Rh[r + S];
            } else {
                int hp  = lane * 8 + r + S;
                bool vp = hp < 256;
                int hpc = vp ? hp : 255;
                int aip = hpc + (hpc >> 3);
                ldh = __float2half2_rn(vp ? pL[aip] : 0.f);
                cdh = __float2half2_rn(vp ? pC[aip] : 0.f);
                rdh = __float2half2_rn(vp ? pR[aip] : 0.f);
            }
            __half2 cch = Ch[r], Lrh = Lh[r], Rrh = Rh[r];

            __half2 A0 = __hmul2(luh, whA[0]);
            A0 = __hfma2(cuh, whA[1], A0); A0 = __hfma2(ruh, whA[2], A0);
            A0 = __hfma2(Lrh, whA[3], A0); A0 = __hfma2(rdh, whA[4], A0);
            A0 = __hfma2(cdh, whA[5], A0); A0 = __hfma2(ldh, whA[6], A0);
            A0 = __hfma2(Rrh, whA[7], A0);
            __half2 B0 = __hmul2(rdh, whA[0]);
            B0 = __hfma2(cdh, whA[1], B0); B0 = __hfma2(ldh, whA[2], B0);
            B0 = __hfma2(Rrh, whA[3], B0); B0 = __hfma2(luh, whA[4], B0);
            B0 = __hfma2(cuh, whA[5], B0); B0 = __hfma2(ruh, whA[6], B0);
            B0 = __hfma2(Lrh, whA[7], B0);
            s[r] = __hmul2(__hsub2(cch, A0), __hsub2(cch, B0));

            __half2 A1 = __hmul2(luh, whB[0]);
            A1 = __hfma2(cuh, whB[1], A1); A1 = __hfma2(ruh, whB[2], A1);
            A1 = __hfma2(Lrh, whB[3], A1); A1 = __hfma2(rdh, whB[4], A1);
            A1 = __hfma2(cdh, whB[5], A1); A1 = __hfma2(ldh, whB[6], A1);
            A1 = __hfma2(Rrh, whB[7], A1);
            __half2 B1 = __hmul2(rdh, whB[0]);
            B1 = __hfma2(cdh, whB[1], B1); B1 = __hfma2(ldh, whB[2], B1);
            B1 = __hfma2(Rrh, whB[3], B1); B1 = __hfma2(luh, whB[4], B1);
            B1 = __hfma2(cuh, whB[5], B1); B1 = __hfma2(ruh, whB[6], B1);
            B1 = __hfma2(Lrh, whB[7], B1);
            t[r] = __hmul2(__hsub2(cch, A1), __hsub2(cch, B1));
        }

        sort256x2h(s, t, lane);

        int e0 = 4 * ep;
        float k40 = k4s[e0 + 0], k41 = k4s[e0 + 1];
        float k42 = k4s[e0 + 2], k43 = k4s[e0 + 3];
        #pragma unroll
        for (int r = 0; r < 8; ++r) {
            float v0 = __low2float(s[r]),  v1 = __high2float(s[r]);
            float v2 = __low2float(t[r]),  v3 = __high2float(t[r]);
            float g0 = 1.f / (1.f + __expf(-v0));
            float g1 = 1.f / (1.f + __expf(-v1));
            float g2 = 1.f / (1.f + __expf(-v2));
            float g3 = 1.f / (1.f + __expf(-v3));
            float a = acc[r];
            a = fmaf(k40 * v0, g0, a);
            a = fmaf(k41 * v1, g1, a);
            a = fmaf(k42 * v2, g2, a);
            a = fmaf(k43 * v3, g3, a);
            acc[r] = a;
        }
    }

    int w = w0 + warp;
    __half* op = g_brh + (size_t)br * BRS + ((size_t)((b * 16 + g) * 256 + w)) * 256;
    __half2 o[4];
    o[0] = __floats2half2_rn(acc[0], acc[1]);
    o[1] = __floats2half2_rn(acc[2], acc[3]);
    o[2] = __floats2half2_rn(acc[4], acc[5]);
    o[3] = __floats2half2_rn(acc[6], acc[7]);
    *reinterpret_cast<uint4*>(op + lane * 8) = *reinterpret_cast<uint4*>(o);
}

// ---------------------------------------------------------------------------
// 3x3 conv on transposed layout with on-the-fly branch combine (max + mean of
// 4 half branch planes) + BN(eval) + SiLU + 1x1 -> sigmoid mask.
__global__ void post_conv(const float* __restrict__ wb,
                          const float* __restrict__ gamma,
                          const float* __restrict__ beta,
                          const float* __restrict__ mean,
                          const float* __restrict__ var,
                          const float* __restrict__ wout,
                          const float* __restrict__ bout) {
    __shared__ float tile[18][35];
    __shared__ float ws[16 * 9];
    int b  = blockIdx.z;
    int o0 = blockIdx.y * 16, i0 = blockIdx.x * 32;
    int tx = threadIdx.x, ty = threadIdx.y;
    int tid = ty * 32 + tx;
    float acc[16][2];
    #pragma unroll
    for (int co = 0; co < 16; ++co) { acc[co][0] = 0.f; acc[co][1] = 0.f; }
    for (int ci = 0; ci < 16; ++ci) {
        __syncthreads();
        for (int i = tid; i < 144; i += 256) {
            int co = i / 9, rc = i % 9;
            int bi = rc / 3, ao = rc % 3;
            ws[co * 9 + ao * 3 + bi] = wb[(co * 16 + ci) * 9 + bi * 3 + ao];
        }
        size_t plane = (size_t)(b * 16 + ci) * HW;
        for (int i = tid; i < 18 * 34; i += 256) {
            int to = i / 34, ti = i - to * 34;
            int oo = o0 + to - 1, ii = i0 + ti - 1;
            float v = 0.f;
            if ((unsigned)oo < 256u && (unsigned)ii < 256u) {
                size_t off = plane + oo * 256 + ii;
                float v0 = __half2float(g_brh[off]);
                float v1 = __half2float(g_brh[BRS + off]);
                float v2 = __half2float(g_brh[2 * (size_t)BRS + off]);
                float v3 = __half2float(g_brh[3 * (size_t)BRS + off]);
                v = fmaxf(fmaxf(v0, v1), fmaxf(v2, v3))
                    + 0.25f * (v0 + v1 + v2 + v3);
            }
            tile[to][ti] = v;
        }
        __syncthreads();
        #pragma unroll
        for (int a = 0; a < 3; ++a)
            #pragma unroll
            for (int bb = 0; bb < 3; ++bb) {
                float v0 = tile[ty + a][tx + bb];
                float v1 = tile[ty + 8 + a][tx + bb];
                #pragma unroll
                for (int co = 0; co < 16; ++co) {
                    float wv = ws[co * 9 + a * 3 + bb];
                    acc[co][0] = fmaf(wv, v0, acc[co][0]);
                    acc[co][1] = fmaf(wv, v1, acc[co][1]);
                }
            }
    }
    float m0 = 0.f, m1 = 0.f;
    #pragma unroll
    for (int co = 0; co < 16; ++co) {
        float sc = __ldg(gamma + co) * rsqrtf(__ldg(var + co) + 1e-5f);
        float sh = __ldg(beta + co) - __ldg(mean + co) * sc;
        float h0 = acc[co][0] * sc + sh;
        float h1 = acc[co][1] * sc + sh;
        h0 = h0 / (1.f + __expf(-h0));
        h1 = h1 / (1.f + __expf(-h1));
        float wv = __ldg(wout + co);
        m0 = fmaf(wv, h0, m0);
        m1 = fmaf(wv, h1, m1);
    }
    float bo = __ldg(bout);
    m0 = 1.f / (1.f + __expf(-(m0 + bo)));
    m1 = 1.f / (1.f + __expf(-(m1 + bo)));
    float* mp = g_mask + (size_t)b * HW + (o0 + ty) * 256 + i0 + tx;
    mp[0]       = m0;
    mp[8 * 256] = m1;
}

// ---------------------------------------------------------------------------
// Final: out = cen * (mask*m*s0 + m*s1 + s2*mask + s3), mask stored [b][w][h].
// Vectorized: each thread handles 4 consecutive w at one h, loops 64 channels
// with float4 loads/stores. Block: 256 threads -> 4 h rows x 256 w.
__global__ void final_kernel(const float* __restrict__ cen,
                             const float* __restrict__ mas,
                             float* __restrict__ out) {
    __shared__ float mt[1024];              // [w][hoff] for this block's 4 rows
    int b  = blockIdx.y;
    int h0 = blockIdx.x * 4;
    int tid = threadIdx.x;
    // load mask tile: i -> w = i>>2, hoff = i&3
    #pragma unroll
    for (int i = tid; i < 1024; i += 256) {
        int wv = i >> 2, hoff = i & 3;
        mt[i] = g_mask[(size_t)b * HW + wv * 256 + h0 + hoff];
    }
    __syncthreads();
    float s0 = g_s1[0], s1 = g_s1[1], s2 = g_s1[2], s3 = g_s1[3];
    int hoff = tid >> 6;                    // 0..3
    int h    = h0 + hoff;
    int wb4  = (tid & 63) * 4;              // base w of this thread's float4
    // per-lane coefficients
    float4 msv = *reinterpret_cast<const float4*>(
        mas + (size_t)b * HW + h * 256 + wb4);
    float coef[4];
    {
        float msa[4] = {msv.x, msv.y, msv.z, msv.w};
        #pragma unroll
        for (int j = 0; j < 4; ++j) {
            float mv = mt[(wb4 + j) * 4 + hoff];
            float m  = 1.f / (1.f + __expf(-msa[j]));
            coef[j] = m * fmaf(mv, s0, s1) + fmaf(s2, mv, s3);
        }
    }
    size_t base = (size_t)b * 64 * HW + (size_t)h * 256 + wb4;
    #pragma unroll 4
    for (int c = 0; c < 64; ++c) {
        size_t o = base + (size_t)c * HW;
        float4 cv = *reinterpret_cast<const float4*>(cen + o);
        cv.x *= coef[0]; cv.y *= coef[1]; cv.z *= coef[2]; cv.w *= coef[3];
        *reinterpret_cast<float4*>(out + o) = cv;
    }
}

// ---------------------------------------------------------------------------
extern "C" void kernel_launch(void* const* d_in, const int* in_sizes, int n_in,
                              void* d_out, int out_size) {
    const float* cen      = (const float*)d_in[0];
    const float* mas      = (const float*)d_in[1];
    const float* w_in     = (const float*)d_in[2];
    const float* b_in     = (const float*)d_in[3];
    const float* w_c0     = (const float*)d_in[4];
    const float* b_c0     = (const float*)d_in[5];
    const float* w_c1     = (const float*)d_in[6];
    const float* b_c1     = (const float*)d_in[7];
    const float* w_c2     = (const float*)d_in[8];
    const float* b_c2     = (const float*)d_in[9];
    const float* w_c3     = (const float*)d_in[10];
    const float* b_c3     = (const float*)d_in[11];
    const float* scales1  = (const float*)d_in[12];
    const float* scales2  = (const float*)d_in[13];
    const float* scales3  = (const float*)d_in[14];
    const float* w_base   = (const float*)d_in[15];
    const float* bn_gamma = (const float*)d_in[16];
    const float* bn_beta  = (const float*)d_in[17];
    const float* bn_mean  = (const float*)d_in[18];
    const float* bn_var   = (const float*)d_in[19];
    const float* w_out    = (const float*)d_in[20];
    const float* b_out    = (const float*)d_in[21];
    float* out = (float*)d_out;

    prep_kernel<<<1, 256>>>(scales1, scales2, scales3);
    in_conv<<<1024, 256>>>(cen, w_in, b_in);

    dim3 cgrid(8, 16, 4), cblk(32, 8);
    dim3 fgrid(32, 16, 4);

    mid_conv<1><<<cgrid, cblk>>>(w_c0, b_c0);
    fused_branch<1><<<fgrid, 256>>>(0);

    mid_conv<3><<<cgrid, cblk>>>(w_c1, b_c1);
    fused_branch<3><<<fgrid, 256>>>(1);

    mid_conv<5><<<cgrid, cblk>>>(w_c2, b_c2);
    fused_branch<5><<<fgrid, 256>>>(2);

    mid_conv<7><<<cgrid, cblk>>>(w_c3, b_c3);
    fused_branch<7><<<fgrid, 256>>>(3);

    post_conv<<<cgrid, cblk>>>(w_base, bn_gamma, bn_beta, bn_mean, bn_var,
                               w_out, b_out);

    final_kernel<<<dim3(64, 4), 256>>>(cen, mas, out);
}